// round 2
// baseline (speedup 1.0000x reference)
#include <cuda_runtime.h>
#include <math.h>

#define NL 4
#define NB 2
#define NS 2048
#define ND 1024
#define NH 16
#define DH 64
#define NV 50257
#define NF 4096
#define MROWS (NB*NS)        // 4096
#define BH (NB*NH)           // 32
#define NT 256

// ---------------- scratch (static device arrays; no allocations) ----------------
__device__ float g_x[MROWS*ND];
__device__ float g_h[MROWS*ND];
__device__ float g_q[MROWS*ND];
__device__ float g_k[MROWS*ND];
__device__ float g_v[MROWS*ND];
__device__ float g_o[MROWS*ND];
__device__ float g_mlp[(size_t)MROWS*NF];
__device__ float g_att[(size_t)BH*NS*NS];        // 512 MB: scores -> att in place
__device__ float g_logits[(size_t)MROWS*NV];     // 823 MB
__device__ float g_rownll[MROWS];

// ---------------- helpers ----------------
__device__ __forceinline__ float block_reduce_sum(float v, float* red) {
    int t = threadIdx.x;
    red[t] = v; __syncthreads();
    for (int o = NT/2; o > 0; o >>= 1) {
        if (t < o) red[t] += red[t + o];
        __syncthreads();
    }
    float r = red[0]; __syncthreads();
    return r;
}
__device__ __forceinline__ float block_reduce_max(float v, float* red) {
    int t = threadIdx.x;
    red[t] = v; __syncthreads();
    for (int o = NT/2; o > 0; o >>= 1) {
        if (t < o) red[t] = fmaxf(red[t], red[t + o]);
        __syncthreads();
    }
    float r = red[0]; __syncthreads();
    return r;
}

// ---------------- kernels ----------------
__global__ void embed_k(const int* __restrict__ tokens, const float* __restrict__ we,
                        const float* __restrict__ pe, float* __restrict__ x) {
    int idx = blockIdx.x * blockDim.x + threadIdx.x;
    if (idx >= MROWS * ND) return;
    int d = idx & (ND - 1);
    int row = idx >> 10;          // ND = 1024
    int s = row & (NS - 1);
    x[idx] = we[(size_t)tokens[row] * ND + d] + pe[(size_t)s * ND + d];
}

__global__ void ln_k(const float* __restrict__ x, const float* __restrict__ w,
                     const float* __restrict__ b, float* __restrict__ out) {
    __shared__ float red[NT];
    int row = blockIdx.x;
    const float* xr = x + (size_t)row * ND;
    float s = 0.f;
    for (int i = threadIdx.x; i < ND; i += NT) s += xr[i];
    float mean = block_reduce_sum(s, red) * (1.f / ND);
    float vs = 0.f;
    for (int i = threadIdx.x; i < ND; i += NT) { float d = xr[i] - mean; vs += d * d; }
    float var = block_reduce_sum(vs, red) * (1.f / ND);
    float rstd = rsqrtf(var + 1e-5f);
    float* outr = out + (size_t)row * ND;
    for (int i = threadIdx.x; i < ND; i += NT)
        outr[i] = (xr[i] - mean) * rstd * w[i] + b[i];
}

// C[M,N] = A[M,K] @ W[K,N] (+bias) (optional exact GELU) (+optional resid)
__global__ __launch_bounds__(NT)
void gemm_k(const float* __restrict__ A, const float* __restrict__ W,
            const float* __restrict__ bias, const float* __restrict__ resid,
            float* __restrict__ C, int M, int K, int N, int act) {
    __shared__ float As[16][65];
    __shared__ float Bs[16][65];
    int tid = threadIdx.x;
    int tx = tid & 15, ty = tid >> 4;
    int row0 = blockIdx.y * 64, col0 = blockIdx.x * 64;
    float acc[4][4] = {};
    for (int k0 = 0; k0 < K; k0 += 16) {
        #pragma unroll
        for (int t = 0; t < 4; t++) {
            int i = tid + t * 256;
            int m = i >> 4, kk = i & 15;
            As[kk][m] = A[(size_t)(row0 + m) * K + k0 + kk];
        }
        #pragma unroll
        for (int t = 0; t < 4; t++) {
            int i = tid + t * 256;
            int kk = i >> 6, n = i & 63;
            int c = col0 + n;
            Bs[kk][n] = (c < N) ? W[(size_t)(k0 + kk) * N + c] : 0.f;
        }
        __syncthreads();
        #pragma unroll
        for (int kk = 0; kk < 16; kk++) {
            float a[4], bb[4];
            #pragma unroll
            for (int i = 0; i < 4; i++) a[i] = As[kk][ty * 4 + i];
            #pragma unroll
            for (int j = 0; j < 4; j++) bb[j] = Bs[kk][tx + 16 * j];
            #pragma unroll
            for (int i = 0; i < 4; i++)
                #pragma unroll
                for (int j = 0; j < 4; j++)
                    acc[i][j] += a[i] * bb[j];
        }
        __syncthreads();
    }
    #pragma unroll
    for (int i = 0; i < 4; i++) {
        int r = row0 + ty * 4 + i;
        #pragma unroll
        for (int j = 0; j < 4; j++) {
            int c = col0 + tx + 16 * j;
            if (c < N) {
                float v2 = acc[i][j];
                if (bias) v2 += bias[c];
                if (act) v2 = 0.5f * v2 * (1.f + erff(v2 * 0.70710678118f));
                if (resid) v2 += resid[(size_t)r * N + c];
                C[(size_t)r * N + c] = v2;
            }
        }
    }
}

__global__ void rope_k(float* __restrict__ x) {   // x: [B,S,H,DH]
    int idx = blockIdx.x * blockDim.x + threadIdx.x;
    if (idx >= NB * NS * NH * 32) return;
    int j = idx & 31;
    int r = idx >> 5;                 // r = (b*S+s)*H+h
    int s = (r >> 4) & (NS - 1);
    float inv = powf(10000.f, -(float)(2 * j) / 64.f);
    float fr = (float)s * inv;
    float sn, cs;
    sincosf(fr, &sn, &cs);
    float* p = x + (size_t)r * DH;
    float x1 = p[j], x2 = p[j + 32];
    p[j]      = x1 * cs - x2 * sn;
    p[j + 32] = x2 * cs + x1 * sn;
}

__global__ __launch_bounds__(NT)
void scores_k(const float* __restrict__ q, const float* __restrict__ k,
              float* __restrict__ att, float scale) {
    int bh = blockIdx.z;
    int b = bh >> 4, h = bh & 15;
    int i0 = blockIdx.y * 64, j0 = blockIdx.x * 64;
    if (j0 > i0) return;                 // tile fully above causal diagonal
    __shared__ float Qs[16][65];
    __shared__ float Ks[16][65];
    int tid = threadIdx.x, tx = tid & 15, ty = tid >> 4;
    float acc[4][4] = {};
    for (int d0 = 0; d0 < DH; d0 += 16) {
        #pragma unroll
        for (int t = 0; t < 4; t++) {
            int idx = tid + t * 256;
            int m = idx >> 4, dd = idx & 15;
            Qs[dd][m] = q[((size_t)(b * NS + i0 + m) * NH + h) * DH + d0 + dd];
            Ks[dd][m] = k[((size_t)(b * NS + j0 + m) * NH + h) * DH + d0 + dd];
        }
        __syncthreads();
        #pragma unroll
        for (int kk = 0; kk < 16; kk++) {
            float a[4], bb[4];
            #pragma unroll
            for (int i = 0; i < 4; i++) a[i] = Qs[kk][ty * 4 + i];
            #pragma unroll
            for (int j = 0; j < 4; j++) bb[j] = Ks[kk][tx + 16 * j];
            #pragma unroll
            for (int i = 0; i < 4; i++)
                #pragma unroll
                for (int j = 0; j < 4; j++)
                    acc[i][j] += a[i] * bb[j];
        }
        __syncthreads();
    }
    #pragma unroll
    for (int i = 0; i < 4; i++) {
        int ii = i0 + ty * 4 + i;
        #pragma unroll
        for (int j = 0; j < 4; j++) {
            int jj = j0 + tx + 16 * j;
            att[((size_t)bh * NS + ii) * NS + jj] = acc[i][j] * scale;
        }
    }
}

__global__ void softmax_k(float* __restrict__ att) {
    __shared__ float red[NT];
    int row = blockIdx.x;            // 0..BH*NS-1
    int i = row & (NS - 1);
    float* p = att + (size_t)row * NS;
    int n = i + 1;
    float m = -1e30f;
    for (int j = threadIdx.x; j < n; j += NT) m = fmaxf(m, p[j]);
    float M = block_reduce_max(m, red);
    float s = 0.f;
    for (int j = threadIdx.x; j < n; j += NT) {
        float e = expf(p[j] - M);
        p[j] = e;
        s += e;
    }
    float S_ = block_reduce_sum(s, red);
    float inv = 1.f / S_;
    for (int j = threadIdx.x; j < n; j += NT) p[j] *= inv;
    for (int j = n + threadIdx.x; j < NS; j += NT) p[j] = 0.f;   // causal zero-fill
}

__global__ __launch_bounds__(NT)
void attv_k(const float* __restrict__ att, const float* __restrict__ v,
            float* __restrict__ o) {
    int bh = blockIdx.z;
    int b = bh >> 4, h = bh & 15;
    int i0 = blockIdx.y * 64;
    __shared__ float As[16][65];   // As[jj][i]
    __shared__ float Vs[16][65];   // Vs[jj][d]
    int tid = threadIdx.x, tx = tid & 15, ty = tid >> 4;
    float acc[4][4] = {};
    int kend = i0 + 64;            // att is zero for j > i, so full tiles are safe
    for (int j0 = 0; j0 < kend; j0 += 16) {
        #pragma unroll
        for (int t = 0; t < 4; t++) {
            int idx = tid + t * 256;
            int m = idx >> 4, jj = idx & 15;
            As[jj][m] = att[((size_t)bh * NS + i0 + m) * NS + j0 + jj];
            int d = idx & 63, jj2 = idx >> 6;
            Vs[jj2][d] = v[((size_t)(b * NS + j0 + jj2) * NH + h) * DH + d];
        }
        __syncthreads();
        #pragma unroll
        for (int kk = 0; kk < 16; kk++) {
            float a[4], bb[4];
            #pragma unroll
            for (int i = 0; i < 4; i++) a[i] = As[kk][ty * 4 + i];
            #pragma unroll
            for (int j = 0; j < 4; j++) bb[j] = Vs[kk][tx + 16 * j];
            #pragma unroll
            for (int i = 0; i < 4; i++)
                #pragma unroll
                for (int j = 0; j < 4; j++)
                    acc[i][j] += a[i] * bb[j];
        }
        __syncthreads();
    }
    #pragma unroll
    for (int i = 0; i < 4; i++) {
        int ii = i0 + ty * 4 + i;
        #pragma unroll
        for (int j = 0; j < 4; j++) {
            int d = tx + 16 * j;
            o[((size_t)(b * NS + ii) * NH + h) * DH + d] = acc[i][j];
        }
    }
}

__global__ void nll_k(const float* __restrict__ logits, const int* __restrict__ targets,
                      float* __restrict__ rownll) {
    __shared__ float red[NT];
    int row = blockIdx.x;
    const float* p = logits + (size_t)row * NV;
    float m = -1e30f;
    for (int j = threadIdx.x; j < NV; j += NT) m = fmaxf(m, p[j]);
    float M = block_reduce_max(m, red);
    float s = 0.f;
    for (int j = threadIdx.x; j < NV; j += NT) s += expf(p[j] - M);
    float S_ = block_reduce_sum(s, red);
    if (threadIdx.x == 0)
        rownll[row] = -(p[targets[row]] - M - logf(S_));
}

__global__ void mean_k(const float* __restrict__ rownll, float* __restrict__ out) {
    __shared__ float red[NT];
    float s = 0.f;
    for (int i = threadIdx.x; i < MROWS; i += NT) s += rownll[i];
    float tot = block_reduce_sum(s, red);
    if (threadIdx.x == 0) out[0] = tot / (float)MROWS;
}

// ---------------- launch ----------------
extern "C" void kernel_launch(void* const* d_in, const int* in_sizes, int n_in,
                              void* d_out, int out_size) {
    const int*   tokens   = (const int*)d_in[0];
    const int*   targets  = (const int*)d_in[1];
    const float* word_emb = (const float*)d_in[2];
    const float* pos_emb  = (const float*)d_in[3];
    const float* ln1_w = (const float*)d_in[4];
    const float* ln1_b = (const float*)d_in[5];
    const float* wq = (const float*)d_in[6];
    const float* bq = (const float*)d_in[7];
    const float* wk = (const float*)d_in[8];
    const float* bk = (const float*)d_in[9];
    const float* wv = (const float*)d_in[10];
    const float* bv = (const float*)d_in[11];
    const float* wo = (const float*)d_in[12];
    const float* bo = (const float*)d_in[13];
    const float* ln2_w = (const float*)d_in[14];
    const float* ln2_b = (const float*)d_in[15];
    const float* w1 = (const float*)d_in[16];
    const float* b1 = (const float*)d_in[17];
    const float* w2 = (const float*)d_in[18];
    const float* b2 = (const float*)d_in[19];
    const float* post_w = (const float*)d_in[20];
    const float* post_b = (const float*)d_in[21];
    const float* lnf_w = (const float*)d_in[22];
    const float* lnf_b = (const float*)d_in[23];
    const float* head_w = (const float*)d_in[24];

    float *x, *h, *q, *k, *v, *o, *mlp, *att, *logits, *rownll;
    cudaGetSymbolAddress((void**)&x, g_x);
    cudaGetSymbolAddress((void**)&h, g_h);
    cudaGetSymbolAddress((void**)&q, g_q);
    cudaGetSymbolAddress((void**)&k, g_k);
    cudaGetSymbolAddress((void**)&v, g_v);
    cudaGetSymbolAddress((void**)&o, g_o);
    cudaGetSymbolAddress((void**)&mlp, g_mlp);
    cudaGetSymbolAddress((void**)&att, g_att);
    cudaGetSymbolAddress((void**)&logits, g_logits);
    cudaGetSymbolAddress((void**)&rownll, g_rownll);

    const float scale = 1.0f / 8.0f;   // 1/sqrt(64)

    embed_k<<<(MROWS * ND + NT - 1) / NT, NT>>>(tokens, word_emb, pos_emb, x);

    for (int l = 0; l < NL; l++) {
        ln_k<<<MROWS, NT>>>(x, ln1_w + l * ND, ln1_b + l * ND, h);

        dim3 gdd(ND / 64, MROWS / 64);
        gemm_k<<<gdd, NT>>>(h, wq + (size_t)l * ND * ND, bq + l * ND, nullptr, q, MROWS, ND, ND, 0);
        gemm_k<<<gdd, NT>>>(h, wk + (size_t)l * ND * ND, bk + l * ND, nullptr, k, MROWS, ND, ND, 0);
        gemm_k<<<gdd, NT>>>(h, wv + (size_t)l * ND * ND, bv + l * ND, nullptr, v, MROWS, ND, ND, 0);

        int nrope = NB * NS * NH * 32;
        rope_k<<<(nrope + NT - 1) / NT, NT>>>(q);
        rope_k<<<(nrope + NT - 1) / NT, NT>>>(k);

        scores_k<<<dim3(NS / 64, NS / 64, BH), NT>>>(q, k, att, scale);
        softmax_k<<<BH * NS, NT>>>(att);
        attv_k<<<dim3(1, NS / 64, BH), NT>>>(att, v, o);

        gemm_k<<<gdd, NT>>>(o, wo + (size_t)l * ND * ND, bo + l * ND, x, x, MROWS, ND, ND, 0);

        ln_k<<<MROWS, NT>>>(x, ln2_w + l * ND, ln2_b + l * ND, h);
        gemm_k<<<dim3(NF / 64, MROWS / 64), NT>>>(h, w1 + (size_t)l * ND * NF, b1 + l * NF,
                                                  nullptr, mlp, MROWS, ND, NF, 1);
        gemm_k<<<gdd, NT>>>(mlp, w2 + (size_t)l * NF * ND, b2 + l * ND, x, x, MROWS, NF, ND, 0);
    }

    // extra post-norm after last block, then final LN
    ln_k<<<MROWS, NT>>>(x, post_w, post_b, h);
    ln_k<<<MROWS, NT>>>(h, lnf_w, lnf_b, x);

    gemm_k<<<dim3((NV + 63) / 64, MROWS / 64), NT>>>(x, head_w, nullptr, nullptr, logits,
                                                     MROWS, ND, NV, 0);

    nll_k<<<MROWS, NT>>>(logits, targets, rownll);
    mean_k<<<1, NT>>>(rownll, (float*)d_out);
}

// round 4
// speedup vs baseline: 1.4254x; 1.4254x over previous
#include <cuda_runtime.h>
#include <math.h>

#define NL 4
#define NB 2
#define NS 2048
#define ND 1024
#define NH 16
#define DH 64
#define NV 50257
#define NF 4096
#define MROWS (NB*NS)        // 4096
#define BH (NB*NH)           // 32
#define NT 256

#define BM 128
#define BN 128
#define BK 16

// ---------------- scratch (static device arrays; no allocations) ----------------
__device__ float g_x[MROWS*ND];
__device__ float g_h[MROWS*ND];
__device__ float g_q[MROWS*ND];
__device__ float g_k[MROWS*ND];
__device__ float g_v[MROWS*ND];
__device__ float g_o[MROWS*ND];
__device__ float g_mlp[(size_t)MROWS*NF];
__device__ float g_att[(size_t)BH*NS*NS];        // 512 MB: scores -> att in place
__device__ float g_logits[(size_t)MROWS*NV];     // 823 MB
__device__ float g_rownll[MROWS];

// ---------------- helpers ----------------
__device__ __forceinline__ float block_reduce_sum(float v, float* red) {
    int t = threadIdx.x;
    red[t] = v; __syncthreads();
    for (int o = NT/2; o > 0; o >>= 1) {
        if (t < o) red[t] += red[t + o];
        __syncthreads();
    }
    float r = red[0]; __syncthreads();
    return r;
}
__device__ __forceinline__ float block_reduce_max(float v, float* red) {
    int t = threadIdx.x;
    red[t] = v; __syncthreads();
    for (int o = NT/2; o > 0; o >>= 1) {
        if (t < o) red[t] = fmaxf(red[t], red[t + o]);
        __syncthreads();
    }
    float r = red[0]; __syncthreads();
    return r;
}

// ---------------- kernels ----------------
__global__ void embed_k(const int* __restrict__ tokens, const float* __restrict__ we,
                        const float* __restrict__ pe, float* __restrict__ x) {
    int idx = blockIdx.x * blockDim.x + threadIdx.x;
    if (idx >= MROWS * ND) return;
    int d = idx & (ND - 1);
    int row = idx >> 10;          // ND = 1024
    int s = row & (NS - 1);
    x[idx] = we[(size_t)tokens[row] * ND + d] + pe[(size_t)s * ND + d];
}

__global__ void ln_k(const float* __restrict__ x, const float* __restrict__ w,
                     const float* __restrict__ b, float* __restrict__ out) {
    __shared__ float red[NT];
    int row = blockIdx.x;
    const float4* xr = (const float4*)(x + (size_t)row * ND);
    float4 v4 = xr[threadIdx.x];
    float s = v4.x + v4.y + v4.z + v4.w;
    float mean = block_reduce_sum(s, red) * (1.f / ND);
    float dx = v4.x - mean, dy = v4.y - mean, dz = v4.z - mean, dw = v4.w - mean;
    float vs = dx*dx + dy*dy + dz*dz + dw*dw;
    float var = block_reduce_sum(vs, red) * (1.f / ND);
    float rstd = rsqrtf(var + 1e-5f);
    float4 w4 = ((const float4*)w)[threadIdx.x];
    float4 b4 = ((const float4*)b)[threadIdx.x];
    float4 o4;
    o4.x = dx * rstd * w4.x + b4.x;
    o4.y = dy * rstd * w4.y + b4.y;
    o4.z = dz * rstd * w4.z + b4.z;
    o4.w = dw * rstd * w4.w + b4.w;
    ((float4*)(out + (size_t)row * ND))[threadIdx.x] = o4;
}

// C[M,N] = A[M,K] @ W[K,N] (+bias) (optional exact GELU) (+optional resid)
// 128x128 tile, BK=16, 256 threads, 8x8 microtile, double-buffered smem.
// W rows may be unaligned for float4 when N % 4 != 0 (head GEMM): scalar path.
__device__ __forceinline__ float4 loadW(const float* __restrict__ W, int krow,
                                        int c, int N, bool v4ok) {
    const float* wp = W + (size_t)krow * N;
    float4 r;
    if (v4ok) {
        r = *(const float4*)(wp + c);
    } else {
        r.x = (c + 0 < N) ? wp[c + 0] : 0.f;
        r.y = (c + 1 < N) ? wp[c + 1] : 0.f;
        r.z = (c + 2 < N) ? wp[c + 2] : 0.f;
        r.w = (c + 3 < N) ? wp[c + 3] : 0.f;
    }
    return r;
}

__global__ __launch_bounds__(256, 2)
void gemm_k(const float* __restrict__ A, const float* __restrict__ W,
            const float* __restrict__ bias, const float* __restrict__ resid,
            float* __restrict__ C, int M, int K, int N, int act) {
    __shared__ __align__(16) float As[2][BK][BM + 4];   // As[buf][k][m]
    __shared__ __align__(16) float Bs[2][BK][BN];       // Bs[buf][k][n]
    int tid = threadIdx.x;
    int tx = tid & 15, ty = tid >> 4;
    int row0 = blockIdx.y * BM, col0 = blockIdx.x * BN;

    // vectorized W loads are legal only if every row start is 16B-aligned
    bool v4ok = ((N & 3) == 0);

    // load index maps
    int aR0 = tid >> 2;            // 0..63  (second: +64)
    int aC  = (tid & 3) * 4;       // 0,4,8,12
    int bR0 = tid >> 5;            // 0..7   (second: +8)
    int bC  = (tid & 31) * 4;      // 0..124

    float4 ra[2], rb[2];
    float acc[8][8] = {};

    int nk = K / BK;

    // prefetch tile 0
    {
        #pragma unroll
        for (int u = 0; u < 2; u++) {
            int r = aR0 + u * 64;
            ra[u] = *(const float4*)(A + (size_t)(row0 + r) * K + aC);
        }
        #pragma unroll
        for (int u = 0; u < 2; u++)
            rb[u] = loadW(W, bR0 + u * 8, col0 + bC, N, v4ok);
        #pragma unroll
        for (int u = 0; u < 2; u++) {
            int r = aR0 + u * 64;
            As[0][aC + 0][r] = ra[u].x;
            As[0][aC + 1][r] = ra[u].y;
            As[0][aC + 2][r] = ra[u].z;
            As[0][aC + 3][r] = ra[u].w;
        }
        #pragma unroll
        for (int u = 0; u < 2; u++) {
            int r = bR0 + u * 8;
            *(float4*)&Bs[0][r][bC] = rb[u];
        }
    }
    __syncthreads();

    int cur = 0;
    for (int t = 0; t < nk; t++) {
        // prefetch next tile into registers
        if (t + 1 < nk) {
            int k0 = (t + 1) * BK;
            #pragma unroll
            for (int u = 0; u < 2; u++) {
                int r = aR0 + u * 64;
                ra[u] = *(const float4*)(A + (size_t)(row0 + r) * K + k0 + aC);
            }
            #pragma unroll
            for (int u = 0; u < 2; u++)
                rb[u] = loadW(W, k0 + bR0 + u * 8, col0 + bC, N, v4ok);
        }

        // compute on current buffer
        #pragma unroll
        for (int kk = 0; kk < BK; kk++) {
            float4 a0 = *(const float4*)&As[cur][kk][ty * 4];
            float4 a1 = *(const float4*)&As[cur][kk][ty * 4 + 64];
            float4 b0 = *(const float4*)&Bs[cur][kk][tx * 4];
            float4 b1 = *(const float4*)&Bs[cur][kk][tx * 4 + 64];
            float av[8] = {a0.x, a0.y, a0.z, a0.w, a1.x, a1.y, a1.z, a1.w};
            float bv[8] = {b0.x, b0.y, b0.z, b0.w, b1.x, b1.y, b1.z, b1.w};
            #pragma unroll
            for (int i = 0; i < 8; i++)
                #pragma unroll
                for (int j = 0; j < 8; j++)
                    acc[i][j] += av[i] * bv[j];
        }

        // store next tile into other buffer
        if (t + 1 < nk) {
            int nxt = cur ^ 1;
            #pragma unroll
            for (int u = 0; u < 2; u++) {
                int r = aR0 + u * 64;
                As[nxt][aC + 0][r] = ra[u].x;
                As[nxt][aC + 1][r] = ra[u].y;
                As[nxt][aC + 2][r] = ra[u].z;
                As[nxt][aC + 3][r] = ra[u].w;
            }
            #pragma unroll
            for (int u = 0; u < 2; u++) {
                int r = bR0 + u * 8;
                *(float4*)&Bs[nxt][r][bC] = rb[u];
            }
        }
        __syncthreads();
        cur ^= 1;
    }

    // epilogue
    #pragma unroll
    for (int i = 0; i < 8; i++) {
        int r = row0 + ty * 4 + (i & 3) + ((i >> 2) * 64);
        #pragma unroll
        for (int j = 0; j < 8; j++) {
            int c = col0 + tx * 4 + (j & 3) + ((j >> 2) * 64);
            if (c < N) {
                float v2 = acc[i][j];
                if (bias) v2 += bias[c];
                if (act) v2 = 0.5f * v2 * (1.f + erff(v2 * 0.70710678118f));
                if (resid) v2 += resid[(size_t)r * N + c];
                C[(size_t)r * N + c] = v2;
            }
        }
    }
}

__global__ void rope_k(float* __restrict__ x) {   // x: [B,S,H,DH]
    int idx = blockIdx.x * blockDim.x + threadIdx.x;
    if (idx >= NB * NS * NH * 32) return;
    int j = idx & 31;
    int r = idx >> 5;                 // r = (b*S+s)*H+h
    int s = (r >> 4) & (NS - 1);
    float inv = powf(10000.f, -(float)(2 * j) / 64.f);
    float fr = (float)s * inv;
    float sn, cs;
    sincosf(fr, &sn, &cs);
    float* p = x + (size_t)r * DH;
    float x1 = p[j], x2 = p[j + 32];
    p[j]      = x1 * cs - x2 * sn;
    p[j + 32] = x2 * cs + x1 * sn;
}

__global__ __launch_bounds__(NT)
void scores_k(const float* __restrict__ q, const float* __restrict__ k,
              float* __restrict__ att, float scale) {
    int bh = blockIdx.z;
    int b = bh >> 4, h = bh & 15;
    int i0 = blockIdx.y * 64, j0 = blockIdx.x * 64;
    if (j0 > i0) return;                 // tile fully above causal diagonal
    __shared__ float Qs[16][65];
    __shared__ float Ks[16][65];
    int tid = threadIdx.x, tx = tid & 15, ty = tid >> 4;
    float acc[4][4] = {};
    for (int d0 = 0; d0 < DH; d0 += 16) {
        #pragma unroll
        for (int t = 0; t < 4; t++) {
            int idx = tid + t * 256;
            int m = idx >> 4, dd = idx & 15;
            Qs[dd][m] = q[((size_t)(b * NS + i0 + m) * NH + h) * DH + d0 + dd];
            Ks[dd][m] = k[((size_t)(b * NS + j0 + m) * NH + h) * DH + d0 + dd];
        }
        __syncthreads();
        #pragma unroll
        for (int kk = 0; kk < 16; kk++) {
            float a[4], bb[4];
            #pragma unroll
            for (int i = 0; i < 4; i++) a[i] = Qs[kk][ty * 4 + i];
            #pragma unroll
            for (int j = 0; j < 4; j++) bb[j] = Ks[kk][tx + 16 * j];
            #pragma unroll
            for (int i = 0; i < 4; i++)
                #pragma unroll
                for (int j = 0; j < 4; j++)
                    acc[i][j] += a[i] * bb[j];
        }
        __syncthreads();
    }
    #pragma unroll
    for (int i = 0; i < 4; i++) {
        int ii = i0 + ty * 4 + i;
        #pragma unroll
        for (int j = 0; j < 4; j++) {
            int jj = j0 + tx + 16 * j;
            att[((size_t)bh * NS + ii) * NS + jj] = acc[i][j] * scale;
        }
    }
}

__global__ void softmax_k(float* __restrict__ att) {
    __shared__ float red[NT];
    int row = blockIdx.x;            // 0..BH*NS-1
    int i = row & (NS - 1);
    float* p = att + (size_t)row * NS;
    int n = i + 1;
    float m = -1e30f;
    for (int j = threadIdx.x; j < n; j += NT) m = fmaxf(m, p[j]);
    float M = block_reduce_max(m, red);
    float s = 0.f;
    for (int j = threadIdx.x; j < n; j += NT) {
        float e = expf(p[j] - M);
        p[j] = e;
        s += e;
    }
    float S_ = block_reduce_sum(s, red);
    float inv = 1.f / S_;
    for (int j = threadIdx.x; j < n; j += NT) p[j] *= inv;
    for (int j = n + threadIdx.x; j < NS; j += NT) p[j] = 0.f;   // causal zero-fill
}

__global__ __launch_bounds__(NT)
void attv_k(const float* __restrict__ att, const float* __restrict__ v,
            float* __restrict__ o) {
    int bh = blockIdx.z;
    int b = bh >> 4, h = bh & 15;
    int i0 = blockIdx.y * 64;
    __shared__ float As[16][65];   // As[jj][i]
    __shared__ float Vs[16][65];   // Vs[jj][d]
    int tid = threadIdx.x, tx = tid & 15, ty = tid >> 4;
    float acc[4][4] = {};
    int kend = i0 + 64;            // att is zero for j > i, so full tiles are safe
    for (int j0 = 0; j0 < kend; j0 += 16) {
        #pragma unroll
        for (int t = 0; t < 4; t++) {
            int idx = tid + t * 256;
            int m = idx >> 4, jj = idx & 15;
            As[jj][m] = att[((size_t)bh * NS + i0 + m) * NS + j0 + jj];
            int d = idx & 63, jj2 = idx >> 6;
            Vs[jj2][d] = v[((size_t)(b * NS + j0 + jj2) * NH + h) * DH + d];
        }
        __syncthreads();
        #pragma unroll
        for (int kk = 0; kk < 16; kk++) {
            float a[4], bb[4];
            #pragma unroll
            for (int i = 0; i < 4; i++) a[i] = As[kk][ty * 4 + i];
            #pragma unroll
            for (int j = 0; j < 4; j++) bb[j] = Vs[kk][tx + 16 * j];
            #pragma unroll
            for (int i = 0; i < 4; i++)
                #pragma unroll
                for (int j = 0; j < 4; j++)
                    acc[i][j] += a[i] * bb[j];
        }
        __syncthreads();
    }
    #pragma unroll
    for (int i = 0; i < 4; i++) {
        int ii = i0 + ty * 4 + i;
        #pragma unroll
        for (int j = 0; j < 4; j++) {
            int d = tx + 16 * j;
            o[((size_t)(b * NS + ii) * NH + h) * DH + d] = acc[i][j];
        }
    }
}

__global__ void nll_k(const float* __restrict__ logits, const int* __restrict__ targets,
                      float* __restrict__ rownll) {
    __shared__ float red[NT];
    int row = blockIdx.x;
    const float* p = logits + (size_t)row * NV;
    float m = -1e30f;
    for (int j = threadIdx.x; j < NV; j += NT) m = fmaxf(m, p[j]);
    float M = block_reduce_max(m, red);
    float s = 0.f;
    for (int j = threadIdx.x; j < NV; j += NT) s += expf(p[j] - M);
    float S_ = block_reduce_sum(s, red);
    if (threadIdx.x == 0)
        rownll[row] = -(p[targets[row]] - M - logf(S_));
}

__global__ void mean_k(const float* __restrict__ rownll, float* __restrict__ out) {
    __shared__ float red[NT];
    float s = 0.f;
    for (int i = threadIdx.x; i < MROWS; i += NT) s += rownll[i];
    float tot = block_reduce_sum(s, red);
    if (threadIdx.x == 0) out[0] = tot / (float)MROWS;
}

// ---------------- launch ----------------
extern "C" void kernel_launch(void* const* d_in, const int* in_sizes, int n_in,
                              void* d_out, int out_size) {
    const int*   tokens   = (const int*)d_in[0];
    const int*   targets  = (const int*)d_in[1];
    const float* word_emb = (const float*)d_in[2];
    const float* pos_emb  = (const float*)d_in[3];
    const float* ln1_w = (const float*)d_in[4];
    const float* ln1_b = (const float*)d_in[5];
    const float* wq = (const float*)d_in[6];
    const float* bq = (const float*)d_in[7];
    const float* wk = (const float*)d_in[8];
    const float* bk = (const float*)d_in[9];
    const float* wv = (const float*)d_in[10];
    const float* bv = (const float*)d_in[11];
    const float* wo = (const float*)d_in[12];
    const float* bo = (const float*)d_in[13];
    const float* ln2_w = (const float*)d_in[14];
    const float* ln2_b = (const float*)d_in[15];
    const float* w1 = (const float*)d_in[16];
    const float* b1 = (const float*)d_in[17];
    const float* w2 = (const float*)d_in[18];
    const float* b2 = (const float*)d_in[19];
    const float* post_w = (const float*)d_in[20];
    const float* post_b = (const float*)d_in[21];
    const float* lnf_w = (const float*)d_in[22];
    const float* lnf_b = (const float*)d_in[23];
    const float* head_w = (const float*)d_in[24];

    float *x, *h, *q, *k, *v, *o, *mlp, *att, *logits, *rownll;
    cudaGetSymbolAddress((void**)&x, g_x);
    cudaGetSymbolAddress((void**)&h, g_h);
    cudaGetSymbolAddress((void**)&q, g_q);
    cudaGetSymbolAddress((void**)&k, g_k);
    cudaGetSymbolAddress((void**)&v, g_v);
    cudaGetSymbolAddress((void**)&o, g_o);
    cudaGetSymbolAddress((void**)&mlp, g_mlp);
    cudaGetSymbolAddress((void**)&att, g_att);
    cudaGetSymbolAddress((void**)&logits, g_logits);
    cudaGetSymbolAddress((void**)&rownll, g_rownll);

    const float scale = 1.0f / 8.0f;   // 1/sqrt(64)

    embed_k<<<(MROWS * ND + NT - 1) / NT, NT>>>(tokens, word_emb, pos_emb, x);

    for (int l = 0; l < NL; l++) {
        ln_k<<<MROWS, NT>>>(x, ln1_w + l * ND, ln1_b + l * ND, h);

        dim3 gdd(ND / BN, MROWS / BM);
        gemm_k<<<gdd, NT>>>(h, wq + (size_t)l * ND * ND, bq + l * ND, nullptr, q, MROWS, ND, ND, 0);
        gemm_k<<<gdd, NT>>>(h, wk + (size_t)l * ND * ND, bk + l * ND, nullptr, k, MROWS, ND, ND, 0);
        gemm_k<<<gdd, NT>>>(h, wv + (size_t)l * ND * ND, bv + l * ND, nullptr, v, MROWS, ND, ND, 0);

        int nrope = NB * NS * NH * 32;
        rope_k<<<(nrope + NT - 1) / NT, NT>>>(q);
        rope_k<<<(nrope + NT - 1) / NT, NT>>>(k);

        scores_k<<<dim3(NS / 64, NS / 64, BH), NT>>>(q, k, att, scale);
        softmax_k<<<BH * NS, NT>>>(att);
        attv_k<<<dim3(1, NS / 64, BH), NT>>>(att, v, o);

        gemm_k<<<gdd, NT>>>(o, wo + (size_t)l * ND * ND, bo + l * ND, x, x, MROWS, ND, ND, 0);

        ln_k<<<MROWS, NT>>>(x, ln2_w + l * ND, ln2_b + l * ND, h);
        gemm_k<<<dim3(NF / BN, MROWS / BM), NT>>>(h, w1 + (size_t)l * ND * NF, b1 + l * NF,
                                                  nullptr, mlp, MROWS, ND, NF, 1);
        gemm_k<<<gdd, NT>>>(mlp, w2 + (size_t)l * NF * ND, b2 + l * ND, x, x, MROWS, NF, ND, 0);
    }

    // extra post-norm after last block, then final LN
    ln_k<<<MROWS, NT>>>(x, post_w, post_b, h);
    ln_k<<<MROWS, NT>>>(h, lnf_w, lnf_b, x);

    gemm_k<<<dim3((NV + BN - 1) / BN, MROWS / BM), NT>>>(x, head_w, nullptr, nullptr, logits,
                                                         MROWS, ND, NV, 0);

    nll_k<<<MROWS, NT>>>(logits, targets, rownll);
    mean_k<<<1, NT>>>(rownll, (float*)d_out);
}

// round 7
// speedup vs baseline: 3.6900x; 2.5887x over previous
#include <cuda_runtime.h>
#include <cuda_bf16.h>
#include <cstdint>
#include <cstddef>
#include <math.h>

typedef unsigned int u32;

#define NL 4
#define NB 2
#define NS 2048
#define ND 1024
#define NH 16
#define DH 64
#define NV 50257
#define NF 4096
#define MROWS (NB*NS)
#define BH (NB*NH)
#define NT 256

#define GBM 128
#define GBN 128
#define GBK 32
#define GP  40

#define WT_L ((size_t)4*ND*ND + (size_t)NF*ND + (size_t)ND*NF)
#define WT_HEAD ((size_t)4*WT_L)

// ---------------- scratch ----------------
__device__ float g_x[MROWS*ND];
__device__ float g_h[MROWS*ND];
__device__ float g_qf[MROWS*ND];
__device__ float g_kf[MROWS*ND];
__device__ float g_att[(size_t)BH*NS*NS];
__device__ float g_logits[(size_t)MROWS*NV];
__device__ float g_rownll[MROWS];

__device__ __nv_bfloat16 g_hb[MROWS*ND];
__device__ __nv_bfloat16 g_qb[MROWS*ND];
__device__ __nv_bfloat16 g_kb[MROWS*ND];
__device__ __nv_bfloat16 g_vb[MROWS*ND];
__device__ __nv_bfloat16 g_ob[MROWS*ND];
__device__ __nv_bfloat16 g_mlpb[(size_t)MROWS*NF];
__device__ __nv_bfloat16 g_wt[WT_HEAD + (size_t)NV*ND];

// ---------------- helpers ----------------
__device__ __forceinline__ float block_reduce_sum(float v, float* red) {
    int t = threadIdx.x;
    red[t] = v; __syncthreads();
    for (int o = NT/2; o > 0; o >>= 1) {
        if (t < o) red[t] += red[t + o];
        __syncthreads();
    }
    float r = red[0]; __syncthreads();
    return r;
}
__device__ __forceinline__ float block_reduce_max(float v, float* red) {
    int t = threadIdx.x;
    red[t] = v; __syncthreads();
    for (int o = NT/2; o > 0; o >>= 1) {
        if (t < o) red[t] = fmaxf(red[t], red[t + o]);
        __syncthreads();
    }
    float r = red[0]; __syncthreads();
    return r;
}

__device__ __forceinline__ void ldm_x4(u32* r, u32 addr) {
    asm volatile("ldmatrix.sync.aligned.m8n8.x4.shared.b16 {%0,%1,%2,%3}, [%4];"
                 : "=r"(r[0]), "=r"(r[1]), "=r"(r[2]), "=r"(r[3]) : "r"(addr));
}
__device__ __forceinline__ void mma_bf16(float* c, const u32* a, const u32* b) {
    asm volatile("mma.sync.aligned.m16n8k16.row.col.f32.bf16.bf16.f32 "
                 "{%0,%1,%2,%3}, {%4,%5,%6,%7}, {%8,%9}, {%0,%1,%2,%3};"
                 : "+f"(c[0]), "+f"(c[1]), "+f"(c[2]), "+f"(c[3])
                 : "r"(a[0]), "r"(a[1]), "r"(a[2]), "r"(a[3]), "r"(b[0]), "r"(b[1]));
}

// ---------------- kernels ----------------
__global__ void embed_k(const int* __restrict__ tokens, const float* __restrict__ we,
                        const float* __restrict__ pe, float* __restrict__ x) {
    int idx = blockIdx.x * blockDim.x + threadIdx.x;
    if (idx >= MROWS * ND) return;
    int d = idx & (ND - 1);
    int row = idx >> 10;
    int s = row & (NS - 1);
    x[idx] = we[(size_t)tokens[row] * ND + d] + pe[(size_t)s * ND + d];
}

// W[K][N] fp32 -> Wt[N][K] bf16
__global__ void convtrans_k(const float* __restrict__ W, __nv_bfloat16* __restrict__ Wt,
                            int K, int N) {
    __shared__ float t[32][33];
    int k0 = blockIdx.y * 32, n0 = blockIdx.x * 32;
    int tx = threadIdx.x, ty = threadIdx.y;
    for (int i = ty; i < 32; i += 8) {
        int n = n0 + tx;
        t[i][tx] = (n < N) ? W[(size_t)(k0 + i) * N + n] : 0.f;
    }
    __syncthreads();
    for (int i = ty; i < 32; i += 8) {
        int n = n0 + i;
        if (n < N) Wt[(size_t)n * K + k0 + tx] = __float2bfloat16(t[tx][i]);
    }
}

__global__ void ln_k(const float* __restrict__ x, const float* __restrict__ w,
                     const float* __restrict__ b, float* __restrict__ outf,
                     __nv_bfloat16* __restrict__ outb) {
    __shared__ float red[NT];
    int row = blockIdx.x;
    const float4* xr = (const float4*)(x + (size_t)row * ND);
    float4 v4 = xr[threadIdx.x];
    float s = v4.x + v4.y + v4.z + v4.w;
    float mean = block_reduce_sum(s, red) * (1.f / ND);
    float dx = v4.x - mean, dy = v4.y - mean, dz = v4.z - mean, dw = v4.w - mean;
    float vs = dx*dx + dy*dy + dz*dz + dw*dw;
    float var = block_reduce_sum(vs, red) * (1.f / ND);
    float rstd = rsqrtf(var + 1e-5f);
    float4 w4 = ((const float4*)w)[threadIdx.x];
    float4 b4 = ((const float4*)b)[threadIdx.x];
    float o0 = dx * rstd * w4.x + b4.x;
    float o1 = dy * rstd * w4.y + b4.y;
    float o2 = dz * rstd * w4.z + b4.z;
    float o3 = dw * rstd * w4.w + b4.w;
    if (outf) {
        float4 o4;
        o4.x = o0; o4.y = o1; o4.z = o2; o4.w = o3;
        ((float4*)(outf + (size_t)row * ND))[threadIdx.x] = o4;
    }
    if (outb) {
        __nv_bfloat16* p = outb + (size_t)row * ND + threadIdx.x * 4;
        p[0] = __float2bfloat16(o0); p[1] = __float2bfloat16(o1);
        p[2] = __float2bfloat16(o2); p[3] = __float2bfloat16(o3);
    }
}

// bf16 tensor-core GEMM: C[M,N] = A[M,K] @ Bt[N,K]^T (+bias)(+gelu)(+resid)
__global__ __launch_bounds__(256)
void gemm_bf(const __nv_bfloat16* __restrict__ A, const __nv_bfloat16* __restrict__ Bt,
             const float* __restrict__ bias, const float* __restrict__ resid,
             float* __restrict__ Cf, __nv_bfloat16* __restrict__ Cb,
             int M, int K, int N, int act) {
    __shared__ __align__(16) __nv_bfloat16 As[2][GBM * GP];
    __shared__ __align__(16) __nv_bfloat16 Bs[2][GBM * GP];
    int tid = threadIdx.x;
    int warp = tid >> 5, lane = tid & 31;
    int wm = (warp & 1) * 64;
    int wn = (warp >> 1) * 32;
    int row0 = blockIdx.y * GBM, col0 = blockIdx.x * GBN;

    int lr = tid >> 2;
    int lk = (tid & 3) * 8;

    uint4 ra0, ra1, rb0, rb1;
    uint4 z4; z4.x = 0u; z4.y = 0u; z4.z = 0u; z4.w = 0u;
    float acc[4][4][4];
    for (int i = 0; i < 4; i++)
        for (int j = 0; j < 4; j++)
            for (int c = 0; c < 4; c++) acc[i][j][c] = 0.f;

    int nk = K / GBK;

    // prefetch tile 0
    ra0 = *(const uint4*)(A + (size_t)(row0 + lr) * K + lk);
    ra1 = *(const uint4*)(A + (size_t)(row0 + lr + 64) * K + lk);
    {
        int n1 = col0 + lr, n2 = col0 + lr + 64;
        rb0 = (n1 < N) ? *(const uint4*)(Bt + (size_t)n1 * K + lk) : z4;
        rb1 = (n2 < N) ? *(const uint4*)(Bt + (size_t)n2 * K + lk) : z4;
    }
    *(uint4*)&As[0][lr * GP + lk] = ra0;
    *(uint4*)&As[0][(lr + 64) * GP + lk] = ra1;
    *(uint4*)&Bs[0][lr * GP + lk] = rb0;
    *(uint4*)&Bs[0][(lr + 64) * GP + lk] = rb1;
    __syncthreads();

    int cur = 0;
    for (int t = 0; t < nk; t++) {
        if (t + 1 < nk) {
            int k0 = (t + 1) * GBK;
            ra0 = *(const uint4*)(A + (size_t)(row0 + lr) * K + k0 + lk);
            ra1 = *(const uint4*)(A + (size_t)(row0 + lr + 64) * K + k0 + lk);
            int n1 = col0 + lr, n2 = col0 + lr + 64;
            rb0 = (n1 < N) ? *(const uint4*)(Bt + (size_t)n1 * K + k0 + lk) : z4;
            rb1 = (n2 < N) ? *(const uint4*)(Bt + (size_t)n2 * K + k0 + lk) : z4;
        }

        u32 aB = (u32)__cvta_generic_to_shared(&As[cur][0]);
        u32 bB = (u32)__cvta_generic_to_shared(&Bs[cur][0]);
        #pragma unroll
        for (int ks = 0; ks < 2; ks++) {
            int kk = ks * 16;
            u32 areg[4][4];
            u32 breg[4][2];
            #pragma unroll
            for (int mi = 0; mi < 4; mi++) {
                int r = wm + mi * 16 + (lane & 15);
                int c = kk + (lane >> 4) * 8;
                ldm_x4(areg[mi], aB + (u32)(r * GP + c) * 2u);
            }
            #pragma unroll
            for (int p = 0; p < 2; p++) {
                int r = wn + p * 16 + ((lane >> 4) << 3) + (lane & 7);
                int c = kk + ((lane >> 3) & 1) * 8;
                u32 tmp[4];
                ldm_x4(tmp, bB + (u32)(r * GP + c) * 2u);
                breg[p * 2][0] = tmp[0]; breg[p * 2][1] = tmp[1];
                breg[p * 2 + 1][0] = tmp[2]; breg[p * 2 + 1][1] = tmp[3];
            }
            #pragma unroll
            for (int mi = 0; mi < 4; mi++)
                #pragma unroll
                for (int nj = 0; nj < 4; nj++)
                    mma_bf16(acc[mi][nj], areg[mi], breg[nj]);
        }

        if (t + 1 < nk) {
            int nxt = cur ^ 1;
            *(uint4*)&As[nxt][lr * GP + lk] = ra0;
            *(uint4*)&As[nxt][(lr + 64) * GP + lk] = ra1;
            *(uint4*)&Bs[nxt][lr * GP + lk] = rb0;
            *(uint4*)&Bs[nxt][(lr + 64) * GP + lk] = rb1;
        }
        __syncthreads();
        cur ^= 1;
    }

    // epilogue
    #pragma unroll
    for (int mi = 0; mi < 4; mi++) {
        int rA = row0 + wm + mi * 16 + (lane >> 2);
        #pragma unroll
        for (int nj = 0; nj < 4; nj++) {
            int cA = col0 + wn + nj * 8 + (lane & 3) * 2;
            #pragma unroll
            for (int hh = 0; hh < 2; hh++) {
                int r = rA + hh * 8;
                #pragma unroll
                for (int cc = 0; cc < 2; cc++) {
                    int c = cA + cc;
                    if (c < N) {
                        float v = acc[mi][nj][hh * 2 + cc];
                        if (bias) v += bias[c];
                        if (act) v = 0.5f * v * (1.f + erff(v * 0.70710678118f));
                        if (resid) v += resid[(size_t)r * N + c];
                        if (Cf) Cf[(size_t)r * N + c] = v;
                        else    Cb[(size_t)r * N + c] = __float2bfloat16(v);
                    }
                }
            }
        }
    }
}

__global__ void rope_k(const float* __restrict__ x, __nv_bfloat16* __restrict__ out) {
    int idx = blockIdx.x * blockDim.x + threadIdx.x;
    if (idx >= NB * NS * NH * 32) return;
    int j = idx & 31;
    int r = idx >> 5;
    int s = (r >> 4) & (NS - 1);
    float inv = powf(10000.f, -(float)(2 * j) / 64.f);
    float fr = (float)s * inv;
    float sn, cs;
    sincosf(fr, &sn, &cs);
    const float* p = x + (size_t)r * DH;
    float x1 = p[j], x2 = p[j + 32];
    out[(size_t)r * DH + j]      = __float2bfloat16(x1 * cs - x2 * sn);
    out[(size_t)r * DH + j + 32] = __float2bfloat16(x2 * cs + x1 * sn);
}

__global__ __launch_bounds__(NT)
void scores_k(const __nv_bfloat16* __restrict__ q, const __nv_bfloat16* __restrict__ k,
              float* __restrict__ att, float scale) {
    int bh = blockIdx.z;
    int b = bh >> 4, h = bh & 15;
    int i0 = blockIdx.y * 64, j0 = blockIdx.x * 64;
    if (j0 > i0) return;
    __shared__ float Qs[16][65];
    __shared__ float Ks[16][65];
    int tid = threadIdx.x, tx = tid & 15, ty = tid >> 4;
    float acc[4][4];
    for (int i = 0; i < 4; i++) for (int j = 0; j < 4; j++) acc[i][j] = 0.f;
    for (int d0 = 0; d0 < DH; d0 += 16) {
        #pragma unroll
        for (int t = 0; t < 4; t++) {
            int idx = tid + t * 256;
            int m = idx >> 4, dd = idx & 15;
            Qs[dd][m] = __bfloat162float(q[((size_t)(b * NS + i0 + m) * NH + h) * DH + d0 + dd]);
            Ks[dd][m] = __bfloat162float(k[((size_t)(b * NS + j0 + m) * NH + h) * DH + d0 + dd]);
        }
        __syncthreads();
        #pragma unroll
        for (int kk = 0; kk < 16; kk++) {
            float a[4], bb[4];
            #pragma unroll
            for (int i = 0; i < 4; i++) a[i] = Qs[kk][ty * 4 + i];
            #pragma unroll
            for (int j = 0; j < 4; j++) bb[j] = Ks[kk][tx + 16 * j];
            #pragma unroll
            for (int i = 0; i < 4; i++)
                #pragma unroll
                for (int j = 0; j < 4; j++)
                    acc[i][j] += a[i] * bb[j];
        }
        __syncthreads();
    }
    #pragma unroll
    for (int i = 0; i < 4; i++) {
        int ii = i0 + ty * 4 + i;
        #pragma unroll
        for (int j = 0; j < 4; j++) {
            int jj = j0 + tx + 16 * j;
            att[((size_t)bh * NS + ii) * NS + jj] = acc[i][j] * scale;
        }
    }
}

__global__ void softmax_k(float* __restrict__ att) {
    __shared__ float red[NT];
    int row = blockIdx.x;
    int i = row & (NS - 1);
    float* p = att + (size_t)row * NS;
    int n = i + 1;
    float m = -1e30f;
    for (int j = threadIdx.x; j < n; j += NT) m = fmaxf(m, p[j]);
    float M = block_reduce_max(m, red);
    float s = 0.f;
    for (int j = threadIdx.x; j < n; j += NT) {
        float e = expf(p[j] - M);
        p[j] = e;
        s += e;
    }
    float S_ = block_reduce_sum(s, red);
    float inv = 1.f / S_;
    for (int j = threadIdx.x; j < n; j += NT) p[j] *= inv;
    for (int j = n + threadIdx.x; j < NS; j += NT) p[j] = 0.f;
}

__global__ __launch_bounds__(NT)
void attv_k(const float* __restrict__ att, const __nv_bfloat16* __restrict__ v,
            __nv_bfloat16* __restrict__ o) {
    int bh = blockIdx.z;
    int b = bh >> 4, h = bh & 15;
    int i0 = blockIdx.y * 64;
    __shared__ float As[16][65];
    __shared__ float Vs[16][65];
    int tid = threadIdx.x, tx = tid & 15, ty = tid >> 4;
    float acc[4][4];
    for (int i = 0; i < 4; i++) for (int j = 0; j < 4; j++) acc[i][j] = 0.f;
    int kend = i0 + 64;
    for (int j0 = 0; j0 < kend; j0 += 16) {
        #pragma unroll
        for (int t = 0; t < 4; t++) {
            int idx = tid + t * 256;
            int m = idx >> 4, jj = idx & 15;
            As[jj][m] = att[((size_t)bh * NS + i0 + m) * NS + j0 + jj];
            int d = idx & 63, jj2 = idx >> 6;
            Vs[jj2][d] = __bfloat162float(v[((size_t)(b * NS + j0 + jj2) * NH + h) * DH + d]);
        }
        __syncthreads();
        #pragma unroll
        for (int kk = 0; kk < 16; kk++) {
            float a[4], bb[4];
            #pragma unroll
            for (int i = 0; i < 4; i++) a[i] = As[kk][ty * 4 + i];
            #pragma unroll
            for (int j = 0; j < 4; j++) bb[j] = Vs[kk][tx + 16 * j];
            #pragma unroll
            for (int i = 0; i < 4; i++)
                #pragma unroll
                for (int j = 0; j < 4; j++)
                    acc[i][j] += a[i] * bb[j];
        }
        __syncthreads();
    }
    #pragma unroll
    for (int i = 0; i < 4; i++) {
        int ii = i0 + ty * 4 + i;
        #pragma unroll
        for (int j = 0; j < 4; j++) {
            int d = tx + 16 * j;
            o[((size_t)(b * NS + ii) * NH + h) * DH + d] = __float2bfloat16(acc[i][j]);
        }
    }
}

__global__ void nll_k(const float* __restrict__ logits, const int* __restrict__ targets,
                      float* __restrict__ rownll) {
    __shared__ float red[NT];
    int row = blockIdx.x;
    const float* p = logits + (size_t)row * NV;
    float m = -1e30f;
    for (int j = threadIdx.x; j < NV; j += NT) m = fmaxf(m, p[j]);
    float M = block_reduce_max(m, red);
    float s = 0.f;
    for (int j = threadIdx.x; j < NV; j += NT) s += expf(p[j] - M);
    float S_ = block_reduce_sum(s, red);
    if (threadIdx.x == 0)
        rownll[row] = -(p[targets[row]] - M - logf(S_));
}

__global__ void mean_k(const float* __restrict__ rownll, float* __restrict__ out) {
    __shared__ float red[NT];
    float s = 0.f;
    for (int i = threadIdx.x; i < MROWS; i += NT) s += rownll[i];
    float tot = block_reduce_sum(s, red);
    if (threadIdx.x == 0) out[0] = tot / (float)MROWS;
}

// ---------------- launch ----------------
extern "C" void kernel_launch(void* const* d_in, const int* in_sizes, int n_in,
                              void* d_out, int out_size) {
    const int*   tokens   = (const int*)d_in[0];
    const int*   targets  = (const int*)d_in[1];
    const float* word_emb = (const float*)d_in[2];
    const float* pos_emb  = (const float*)d_in[3];
    const float* ln1_w = (const float*)d_in[4];
    const float* ln1_b = (const float*)d_in[5];
    const float* wq = (const float*)d_in[6];
    const float* bq = (const float*)d_in[7];
    const float* wk = (const float*)d_in[8];
    const float* bk = (const float*)d_in[9];
    const float* wv = (const float*)d_in[10];
    const float* bv = (const float*)d_in[11];
    const float* wo = (const float*)d_in[12];
    const float* bo = (const float*)d_in[13];
    const float* ln2_w = (const float*)d_in[14];
    const float* ln2_b = (const float*)d_in[15];
    const float* w1 = (const float*)d_in[16];
    const float* b1 = (const float*)d_in[17];
    const float* w2 = (const float*)d_in[18];
    const float* b2 = (const float*)d_in[19];
    const float* post_w = (const float*)d_in[20];
    const float* post_b = (const float*)d_in[21];
    const float* lnf_w = (const float*)d_in[22];
    const float* lnf_b = (const float*)d_in[23];
    const float* head_w = (const float*)d_in[24];

    float *x, *h, *qf, *kf, *att, *logits, *rownll;
    __nv_bfloat16 *hb, *qb, *kb, *vb, *ob, *mlpb, *wt;
    cudaGetSymbolAddress((void**)&x, g_x);
    cudaGetSymbolAddress((void**)&h, g_h);
    cudaGetSymbolAddress((void**)&qf, g_qf);
    cudaGetSymbolAddress((void**)&kf, g_kf);
    cudaGetSymbolAddress((void**)&att, g_att);
    cudaGetSymbolAddress((void**)&logits, g_logits);
    cudaGetSymbolAddress((void**)&rownll, g_rownll);
    cudaGetSymbolAddress((void**)&hb, g_hb);
    cudaGetSymbolAddress((void**)&qb, g_qb);
    cudaGetSymbolAddress((void**)&kb, g_kb);
    cudaGetSymbolAddress((void**)&vb, g_vb);
    cudaGetSymbolAddress((void**)&ob, g_ob);
    cudaGetSymbolAddress((void**)&mlpb, g_mlpb);
    cudaGetSymbolAddress((void**)&wt, g_wt);

    const float scale = 1.0f / 8.0f;
    dim3 tb(32, 8);

    for (int l = 0; l < NL; l++) {
        __nv_bfloat16* base = wt + (size_t)l * WT_L;
        convtrans_k<<<dim3(ND/32, ND/32), tb>>>(wq + (size_t)l*ND*ND, base, ND, ND);
        convtrans_k<<<dim3(ND/32, ND/32), tb>>>(wk + (size_t)l*ND*ND, base + (size_t)ND*ND, ND, ND);
        convtrans_k<<<dim3(ND/32, ND/32), tb>>>(wv + (size_t)l*ND*ND, base + (size_t)2*ND*ND, ND, ND);
        convtrans_k<<<dim3(ND/32, ND/32), tb>>>(wo + (size_t)l*ND*ND, base + (size_t)3*ND*ND, ND, ND);
        convtrans_k<<<dim3(NF/32, ND/32), tb>>>(w1 + (size_t)l*ND*NF, base + (size_t)4*ND*ND, ND, NF);
        convtrans_k<<<dim3(ND/32, NF/32), tb>>>(w2 + (size_t)l*NF*ND, base + (size_t)4*ND*ND + (size_t)NF*ND, NF, ND);
    }
    convtrans_k<<<dim3((NV + 31)/32, ND/32), tb>>>(head_w, wt + WT_HEAD, ND, NV);

    embed_k<<<(MROWS * ND + NT - 1) / NT, NT>>>(tokens, word_emb, pos_emb, x);

    dim3 gdd(ND / GBN, MROWS / GBM);
    for (int l = 0; l < NL; l++) {
        __nv_bfloat16* base = wt + (size_t)l * WT_L;
        __nv_bfloat16* qt  = base;
        __nv_bfloat16* kt  = base + (size_t)ND*ND;
        __nv_bfloat16* vt  = base + (size_t)2*ND*ND;
        __nv_bfloat16* wot = base + (size_t)3*ND*ND;
        __nv_bfloat16* w1t = base + (size_t)4*ND*ND;
        __nv_bfloat16* w2t = base + (size_t)4*ND*ND + (size_t)NF*ND;

        ln_k<<<MROWS, NT>>>(x, ln1_w + l * ND, ln1_b + l * ND, (float*)0, hb);

        gemm_bf<<<gdd, 256>>>(hb, qt, bq + l * ND, (const float*)0, qf, (__nv_bfloat16*)0, MROWS, ND, ND, 0);
        gemm_bf<<<gdd, 256>>>(hb, kt, bk + l * ND, (const float*)0, kf, (__nv_bfloat16*)0, MROWS, ND, ND, 0);
        gemm_bf<<<gdd, 256>>>(hb, vt, bv + l * ND, (const float*)0, (float*)0, vb, MROWS, ND, ND, 0);

        int nrope = NB * NS * NH * 32;
        rope_k<<<(nrope + NT - 1) / NT, NT>>>(qf, qb);
        rope_k<<<(nrope + NT - 1) / NT, NT>>>(kf, kb);

        scores_k<<<dim3(NS / 64, NS / 64, BH), NT>>>(qb, kb, att, scale);
        softmax_k<<<BH * NS, NT>>>(att);
        attv_k<<<dim3(1, NS / 64, BH), NT>>>(att, vb, ob);

        gemm_bf<<<gdd, 256>>>(ob, wot, bo + l * ND, x, x, (__nv_bfloat16*)0, MROWS, ND, ND, 0);

        ln_k<<<MROWS, NT>>>(x, ln2_w + l * ND, ln2_b + l * ND, (float*)0, hb);
        gemm_bf<<<dim3(NF / GBN, MROWS / GBM), 256>>>(hb, w1t, b1 + l * NF, (const float*)0,
                                                      (float*)0, mlpb, MROWS, ND, NF, 1);
        gemm_bf<<<gdd, 256>>>(mlpb, w2t, b2 + l * ND, x, x, (__nv_bfloat16*)0, MROWS, NF, ND, 0);
    }

    ln_k<<<MROWS, NT>>>(x, post_w, post_b, h, (__nv_bfloat16*)0);
    ln_k<<<MROWS, NT>>>(h, lnf_w, lnf_b, (float*)0, hb);

    gemm_bf<<<dim3((NV + GBN - 1) / GBN, MROWS / GBM), 256>>>(hb, wt + WT_HEAD, (const float*)0,
                                                              (const float*)0, logits,
                                                              (__nv_bfloat16*)0, MROWS, ND, NV, 0);

    nll_k<<<MROWS, NT>>>(logits, targets, rownll);
    mean_k<<<1, NT>>>(rownll, (float*)d_out);
}

// round 9
// speedup vs baseline: 6.0333x; 1.6350x over previous
#include <cuda_runtime.h>
#include <cuda_bf16.h>
#include <cstdint>
#include <cstddef>
#include <math.h>

typedef unsigned int u32;

#define NL 4
#define NB 2
#define NS 2048
#define ND 1024
#define NH 16
#define DH 64
#define NV 50257
#define NF 4096
#define MROWS (NB*NS)
#define BH (NB*NH)
#define NT 256

#define GBM 128
#define GBN 128
#define GBK 32
#define GP  40

#define WT_L ((size_t)4*ND*ND + (size_t)NF*ND + (size_t)ND*NF)
#define WT_HEAD ((size_t)4*WT_L)

// ---------------- scratch ----------------
__device__ float g_x[MROWS*ND];
__device__ float g_h[MROWS*ND];
__device__ float g_qf[MROWS*ND];
__device__ float g_kf[MROWS*ND];
__device__ float g_logits[(size_t)MROWS*NV];
__device__ float g_rownll[MROWS];

__device__ __nv_bfloat16 g_hb[MROWS*ND];
__device__ __nv_bfloat16 g_qb[MROWS*ND];
__device__ __nv_bfloat16 g_kb[MROWS*ND];
__device__ __nv_bfloat16 g_vb[MROWS*ND];
__device__ __nv_bfloat16 g_ob[MROWS*ND];
__device__ __nv_bfloat16 g_mlpb[(size_t)MROWS*NF];
__device__ __nv_bfloat16 g_wt[WT_HEAD + (size_t)NV*ND];

// ---------------- helpers ----------------
__device__ __forceinline__ float block_reduce_sum(float v, float* red) {
    int t = threadIdx.x;
    red[t] = v; __syncthreads();
    for (int o = NT/2; o > 0; o >>= 1) {
        if (t < o) red[t] += red[t + o];
        __syncthreads();
    }
    float r = red[0]; __syncthreads();
    return r;
}
__device__ __forceinline__ float block_reduce_max(float v, float* red) {
    int t = threadIdx.x;
    red[t] = v; __syncthreads();
    for (int o = NT/2; o > 0; o >>= 1) {
        if (t < o) red[t] = fmaxf(red[t], red[t + o]);
        __syncthreads();
    }
    float r = red[0]; __syncthreads();
    return r;
}

__device__ __forceinline__ void ldm_x4(u32* r, u32 addr) {
    asm volatile("ldmatrix.sync.aligned.m8n8.x4.shared.b16 {%0,%1,%2,%3}, [%4];"
                 : "=r"(r[0]), "=r"(r[1]), "=r"(r[2]), "=r"(r[3]) : "r"(addr));
}
__device__ __forceinline__ void mma_bf16(float* c, const u32* a, const u32* b) {
    asm volatile("mma.sync.aligned.m16n8k16.row.col.f32.bf16.bf16.f32 "
                 "{%0,%1,%2,%3}, {%4,%5,%6,%7}, {%8,%9}, {%0,%1,%2,%3};"
                 : "+f"(c[0]), "+f"(c[1]), "+f"(c[2]), "+f"(c[3])
                 : "r"(a[0]), "r"(a[1]), "r"(a[2]), "r"(a[3]), "r"(b[0]), "r"(b[1]));
}
__device__ __forceinline__ u32 pack_bf2(float a, float b) {
    __nv_bfloat162 t = __floats2bfloat162_rn(a, b);
    return *(u32*)&t;
}

// ---------------- kernels ----------------
__global__ void embed_k(const int* __restrict__ tokens, const float* __restrict__ we,
                        const float* __restrict__ pe, float* __restrict__ x) {
    int idx = blockIdx.x * blockDim.x + threadIdx.x;
    if (idx >= MROWS * ND) return;
    int d = idx & (ND - 1);
    int row = idx >> 10;
    int s = row & (NS - 1);
    x[idx] = we[(size_t)tokens[row] * ND + d] + pe[(size_t)s * ND + d];
}

// W[K][N] fp32 -> Wt[N][K] bf16
__global__ void convtrans_k(const float* __restrict__ W, __nv_bfloat16* __restrict__ Wt,
                            int K, int N) {
    __shared__ float t[32][33];
    int k0 = blockIdx.y * 32, n0 = blockIdx.x * 32;
    int tx = threadIdx.x, ty = threadIdx.y;
    for (int i = ty; i < 32; i += 8) {
        int n = n0 + tx;
        t[i][tx] = (n < N) ? W[(size_t)(k0 + i) * N + n] : 0.f;
    }
    __syncthreads();
    for (int i = ty; i < 32; i += 8) {
        int n = n0 + i;
        if (n < N) Wt[(size_t)n * K + k0 + tx] = __float2bfloat16(t[tx][i]);
    }
}

__global__ void ln_k(const float* __restrict__ x, const float* __restrict__ w,
                     const float* __restrict__ b, float* __restrict__ outf,
                     __nv_bfloat16* __restrict__ outb) {
    __shared__ float red[NT];
    int row = blockIdx.x;
    const float4* xr = (const float4*)(x + (size_t)row * ND);
    float4 v4 = xr[threadIdx.x];
    float s = v4.x + v4.y + v4.z + v4.w;
    float mean = block_reduce_sum(s, red) * (1.f / ND);
    float dx = v4.x - mean, dy = v4.y - mean, dz = v4.z - mean, dw = v4.w - mean;
    float vs = dx*dx + dy*dy + dz*dz + dw*dw;
    float var = block_reduce_sum(vs, red) * (1.f / ND);
    float rstd = rsqrtf(var + 1e-5f);
    float4 w4 = ((const float4*)w)[threadIdx.x];
    float4 b4 = ((const float4*)b)[threadIdx.x];
    float o0 = dx * rstd * w4.x + b4.x;
    float o1 = dy * rstd * w4.y + b4.y;
    float o2 = dz * rstd * w4.z + b4.z;
    float o3 = dw * rstd * w4.w + b4.w;
    if (outf) {
        float4 o4;
        o4.x = o0; o4.y = o1; o4.z = o2; o4.w = o3;
        ((float4*)(outf + (size_t)row * ND))[threadIdx.x] = o4;
    }
    if (outb) {
        __nv_bfloat16* p = outb + (size_t)row * ND + threadIdx.x * 4;
        p[0] = __float2bfloat16(o0); p[1] = __float2bfloat16(o1);
        p[2] = __float2bfloat16(o2); p[3] = __float2bfloat16(o3);
    }
}

// bf16 tensor-core GEMM: C[M,N] = A[M,K] @ Bt[N,K]^T (+bias)(+gelu)(+resid)
__global__ __launch_bounds__(256)
void gemm_bf(const __nv_bfloat16* __restrict__ A, const __nv_bfloat16* __restrict__ Bt,
             const float* __restrict__ bias, const float* __restrict__ resid,
             float* __restrict__ Cf, __nv_bfloat16* __restrict__ Cb,
             int M, int K, int N, int act) {
    __shared__ __align__(16) __nv_bfloat16 As[2][GBM * GP];
    __shared__ __align__(16) __nv_bfloat16 Bs[2][GBM * GP];
    int tid = threadIdx.x;
    int warp = tid >> 5, lane = tid & 31;
    int wm = (warp & 1) * 64;
    int wn = (warp >> 1) * 32;
    int row0 = blockIdx.y * GBM, col0 = blockIdx.x * GBN;

    int lr = tid >> 2;
    int lk = (tid & 3) * 8;

    uint4 ra0, ra1, rb0, rb1;
    uint4 z4; z4.x = 0u; z4.y = 0u; z4.z = 0u; z4.w = 0u;
    float acc[4][4][4];
    for (int i = 0; i < 4; i++)
        for (int j = 0; j < 4; j++)
            for (int c = 0; c < 4; c++) acc[i][j][c] = 0.f;

    int nk = K / GBK;

    ra0 = *(const uint4*)(A + (size_t)(row0 + lr) * K + lk);
    ra1 = *(const uint4*)(A + (size_t)(row0 + lr + 64) * K + lk);
    {
        int n1 = col0 + lr, n2 = col0 + lr + 64;
        rb0 = (n1 < N) ? *(const uint4*)(Bt + (size_t)n1 * K + lk) : z4;
        rb1 = (n2 < N) ? *(const uint4*)(Bt + (size_t)n2 * K + lk) : z4;
    }
    *(uint4*)&As[0][lr * GP + lk] = ra0;
    *(uint4*)&As[0][(lr + 64) * GP + lk] = ra1;
    *(uint4*)&Bs[0][lr * GP + lk] = rb0;
    *(uint4*)&Bs[0][(lr + 64) * GP + lk] = rb1;
    __syncthreads();

    int cur = 0;
    for (int t = 0; t < nk; t++) {
        if (t + 1 < nk) {
            int k0 = (t + 1) * GBK;
            ra0 = *(const uint4*)(A + (size_t)(row0 + lr) * K + k0 + lk);
            ra1 = *(const uint4*)(A + (size_t)(row0 + lr + 64) * K + k0 + lk);
            int n1 = col0 + lr, n2 = col0 + lr + 64;
            rb0 = (n1 < N) ? *(const uint4*)(Bt + (size_t)n1 * K + k0 + lk) : z4;
            rb1 = (n2 < N) ? *(const uint4*)(Bt + (size_t)n2 * K + k0 + lk) : z4;
        }

        u32 aB = (u32)__cvta_generic_to_shared(&As[cur][0]);
        u32 bB = (u32)__cvta_generic_to_shared(&Bs[cur][0]);
        #pragma unroll
        for (int ks = 0; ks < 2; ks++) {
            int kk = ks * 16;
            u32 areg[4][4];
            u32 breg[4][2];
            #pragma unroll
            for (int mi = 0; mi < 4; mi++) {
                int r = wm + mi * 16 + (lane & 15);
                int c = kk + (lane >> 4) * 8;
                ldm_x4(areg[mi], aB + (u32)(r * GP + c) * 2u);
            }
            #pragma unroll
            for (int p = 0; p < 2; p++) {
                int r = wn + p * 16 + ((lane >> 4) << 3) + (lane & 7);
                int c = kk + ((lane >> 3) & 1) * 8;
                u32 tmp[4];
                ldm_x4(tmp, bB + (u32)(r * GP + c) * 2u);
                breg[p * 2][0] = tmp[0]; breg[p * 2][1] = tmp[1];
                breg[p * 2 + 1][0] = tmp[2]; breg[p * 2 + 1][1] = tmp[3];
            }
            #pragma unroll
            for (int mi = 0; mi < 4; mi++)
                #pragma unroll
                for (int nj = 0; nj < 4; nj++)
                    mma_bf16(acc[mi][nj], areg[mi], breg[nj]);
        }

        if (t + 1 < nk) {
            int nxt = cur ^ 1;
            *(uint4*)&As[nxt][lr * GP + lk] = ra0;
            *(uint4*)&As[nxt][(lr + 64) * GP + lk] = ra1;
            *(uint4*)&Bs[nxt][lr * GP + lk] = rb0;
            *(uint4*)&Bs[nxt][(lr + 64) * GP + lk] = rb1;
        }
        __syncthreads();
        cur ^= 1;
    }

    #pragma unroll
    for (int mi = 0; mi < 4; mi++) {
        int rA = row0 + wm + mi * 16 + (lane >> 2);
        #pragma unroll
        for (int nj = 0; nj < 4; nj++) {
            int cA = col0 + wn + nj * 8 + (lane & 3) * 2;
            #pragma unroll
            for (int hh = 0; hh < 2; hh++) {
                int r = rA + hh * 8;
                #pragma unroll
                for (int cc = 0; cc < 2; cc++) {
                    int c = cA + cc;
                    if (c < N) {
                        float v = acc[mi][nj][hh * 2 + cc];
                        if (bias) v += bias[c];
                        if (act) v = 0.5f * v * (1.f + erff(v * 0.70710678118f));
                        if (resid) v += resid[(size_t)r * N + c];
                        if (Cf) Cf[(size_t)r * N + c] = v;
                        else    Cb[(size_t)r * N + c] = __float2bfloat16(v);
                    }
                }
            }
        }
    }
}

__global__ void rope_k(const float* __restrict__ x, __nv_bfloat16* __restrict__ out) {
    int idx = blockIdx.x * blockDim.x + threadIdx.x;
    if (idx >= NB * NS * NH * 32) return;
    int j = idx & 31;
    int r = idx >> 5;
    int s = (r >> 4) & (NS - 1);
    float inv = powf(10000.f, -(float)(2 * j) / 64.f);
    float fr = (float)s * inv;
    float sn, cs;
    sincosf(fr, &sn, &cs);
    const float* p = x + (size_t)r * DH;
    float x1 = p[j], x2 = p[j + 32];
    out[(size_t)r * DH + j]      = __float2bfloat16(x1 * cs - x2 * sn);
    out[(size_t)r * DH + j + 32] = __float2bfloat16(x2 * cs + x1 * sn);
}

// -------- fused flash attention (causal), 128-row q tiles, 8 warps --------
// q,k,v,o layout: [((b*NS+s)*NH+h)*DH + d], bf16
__global__ __launch_bounds__(256)
void flash_k(const __nv_bfloat16* __restrict__ q, const __nv_bfloat16* __restrict__ kk_,
             const __nv_bfloat16* __restrict__ v, __nv_bfloat16* __restrict__ o,
             float scale) {
    __shared__ __align__(16) __nv_bfloat16 Ks[128 * 72];
    __shared__ __align__(16) __nv_bfloat16 Vs[64 * 136];
    int bh = blockIdx.y;
    int b = bh >> 4, h = bh & 15;
    int i0 = blockIdx.x * 128;
    int tid = threadIdx.x, warp = tid >> 5, lane = tid & 31;
    int wr = warp * 16;
    int colb = (lane & 3) * 2;
    int rq = lane >> 2;                 // row-in-16 (low half); +8 = high half

    u32 ksBase = (u32)__cvta_generic_to_shared(Ks);
    u32 vsBase = (u32)__cvta_generic_to_shared(Vs);

    // load Q tile into Ks buffer, pull A fragments into registers
    #pragma unroll
    for (int u = 0; u < 4; u++) {
        int idx = tid + u * 256;
        int row = idx >> 3, c = (idx & 7) * 8;
        *(uint4*)&Ks[row * 72 + c] =
            *(const uint4*)(q + (size_t)((b * NS + i0 + row) * NH + h) * DH + c);
    }
    __syncthreads();
    u32 qf[4][4];
    #pragma unroll
    for (int kt = 0; kt < 4; kt++) {
        int r = wr + (lane & 15);
        int c = kt * 16 + (lane >> 4) * 8;
        ldm_x4(qf[kt], ksBase + (u32)(r * 72 + c) * 2u);
    }
    __syncthreads();

    float m_lo = -1e30f, m_hi = -1e30f, l_lo = 0.f, l_hi = 0.f;
    float oa[8][4];
    #pragma unroll
    for (int i = 0; i < 8; i++)
        #pragma unroll
        for (int c = 0; c < 4; c++) oa[i][c] = 0.f;

    for (int j0 = 0; j0 <= i0; j0 += 128) {
        // K tile -> Ks; V tile transposed -> Vs[d][token]
        #pragma unroll
        for (int u = 0; u < 4; u++) {
            int idx = tid + u * 256;
            int row = idx >> 3, c = (idx & 7) * 8;
            *(uint4*)&Ks[row * 72 + c] =
                *(const uint4*)(kk_ + (size_t)((b * NS + j0 + row) * NH + h) * DH + c);
        }
        #pragma unroll
        for (int u = 0; u < 4; u++) {
            int dc = (tid >> 7) + u * 2;        // 0..7
            int token = tid & 127;
            uint4 vv = *(const uint4*)(v + (size_t)((b * NS + j0 + token) * NH + h) * DH + dc * 8);
            __nv_bfloat16 tv[8];
            *(uint4*)tv = vv;
            #pragma unroll
            for (int e = 0; e < 8; e++)
                Vs[(dc * 8 + e) * 136 + token] = tv[e];
        }
        __syncthreads();

        // S = Q K^T   (16 rows per warp x 128 cols)
        float sa[16][4];
        #pragma unroll
        for (int i = 0; i < 16; i++)
            #pragma unroll
            for (int c = 0; c < 4; c++) sa[i][c] = 0.f;
        #pragma unroll
        for (int p = 0; p < 8; p++) {
            #pragma unroll
            for (int kt = 0; kt < 4; kt++) {
                u32 tmp[4];
                int r = p * 16 + ((lane >> 4) << 3) + (lane & 7);
                int c = kt * 16 + ((lane >> 3) & 1) * 8;
                ldm_x4(tmp, ksBase + (u32)(r * 72 + c) * 2u);
                u32 br0[2], br1[2];
                br0[0] = tmp[0]; br0[1] = tmp[1];
                br1[0] = tmp[2]; br1[1] = tmp[3];
                mma_bf16(sa[p * 2], qf[kt], br0);
                mma_bf16(sa[p * 2 + 1], qf[kt], br1);
            }
        }

        // scale + causal mask (diag tile only) + tile row-max
        bool diag = (j0 == i0);
        float tmax_lo = -1e30f, tmax_hi = -1e30f;
        #pragma unroll
        for (int nt = 0; nt < 16; nt++) {
            #pragma unroll
            for (int cc = 0; cc < 4; cc++) {
                float val = sa[nt][cc] * scale;
                if (diag) {
                    int col = nt * 8 + colb + (cc & 1);
                    int row = wr + rq + ((cc >> 1) << 3);
                    if (col > row) val = -1e30f;
                }
                sa[nt][cc] = val;
                if (cc < 2) tmax_lo = fmaxf(tmax_lo, val);
                else        tmax_hi = fmaxf(tmax_hi, val);
            }
        }
        tmax_lo = fmaxf(tmax_lo, __shfl_xor_sync(0xffffffffu, tmax_lo, 1));
        tmax_lo = fmaxf(tmax_lo, __shfl_xor_sync(0xffffffffu, tmax_lo, 2));
        tmax_hi = fmaxf(tmax_hi, __shfl_xor_sync(0xffffffffu, tmax_hi, 1));
        tmax_hi = fmaxf(tmax_hi, __shfl_xor_sync(0xffffffffu, tmax_hi, 2));

        float mn_lo = fmaxf(m_lo, tmax_lo);
        float mn_hi = fmaxf(m_hi, tmax_hi);
        float al_lo = expf(m_lo - mn_lo);
        float al_hi = expf(m_hi - mn_hi);
        m_lo = mn_lo; m_hi = mn_hi;

        float rs_lo = 0.f, rs_hi = 0.f;
        u32 pa[8][4];
        #pragma unroll
        for (int nt = 0; nt < 16; nt++) {
            float p0 = expf(sa[nt][0] - mn_lo);
            float p1 = expf(sa[nt][1] - mn_lo);
            float p2 = expf(sa[nt][2] - mn_hi);
            float p3 = expf(sa[nt][3] - mn_hi);
            rs_lo += p0 + p1;
            rs_hi += p2 + p3;
            pa[nt >> 1][(nt & 1) * 2 + 0] = pack_bf2(p0, p1);
            pa[nt >> 1][(nt & 1) * 2 + 1] = pack_bf2(p2, p3);
        }
        rs_lo += __shfl_xor_sync(0xffffffffu, rs_lo, 1);
        rs_lo += __shfl_xor_sync(0xffffffffu, rs_lo, 2);
        rs_hi += __shfl_xor_sync(0xffffffffu, rs_hi, 1);
        rs_hi += __shfl_xor_sync(0xffffffffu, rs_hi, 2);
        l_lo = l_lo * al_lo + rs_lo;
        l_hi = l_hi * al_hi + rs_hi;

        #pragma unroll
        for (int nt = 0; nt < 8; nt++) {
            oa[nt][0] *= al_lo; oa[nt][1] *= al_lo;
            oa[nt][2] *= al_hi; oa[nt][3] *= al_hi;
        }

        // O += P V   (K dim = 128 tokens, N = 64 head dims)
        #pragma unroll
        for (int np = 0; np < 4; np++) {
            #pragma unroll
            for (int kt = 0; kt < 8; kt++) {
                u32 tmp[4];
                int r = np * 16 + ((lane >> 4) << 3) + (lane & 7);   // d rows of Vs
                int c = kt * 16 + ((lane >> 3) & 1) * 8;             // token cols
                ldm_x4(tmp, vsBase + (u32)(r * 136 + c) * 2u);
                u32 br0[2], br1[2];
                br0[0] = tmp[0]; br0[1] = tmp[1];
                br1[0] = tmp[2]; br1[1] = tmp[3];
                mma_bf16(oa[np * 2], pa[kt], br0);
                mma_bf16(oa[np * 2 + 1], pa[kt], br1);
            }
        }
        __syncthreads();
    }

    // finalize: O /= l, write bf16 pairs
    float il_lo = 1.f / l_lo, il_hi = 1.f / l_hi;
    int row_lo = i0 + wr + rq;
    #pragma unroll
    for (int nt = 0; nt < 8; nt++) {
        int col = nt * 8 + colb;
        u32 lo2 = pack_bf2(oa[nt][0] * il_lo, oa[nt][1] * il_lo);
        u32 hi2 = pack_bf2(oa[nt][2] * il_hi, oa[nt][3] * il_hi);
        *(u32*)(o + (size_t)((b * NS + row_lo) * NH + h) * DH + col) = lo2;
        *(u32*)(o + (size_t)((b * NS + row_lo + 8) * NH + h) * DH + col) = hi2;
    }
}

__global__ void nll_k(const float* __restrict__ logits, const int* __restrict__ targets,
                      float* __restrict__ rownll) {
    __shared__ float red[NT];
    int row = blockIdx.x;
    const float* p = logits + (size_t)row * NV;
    float m = -1e30f;
    for (int j = threadIdx.x; j < NV; j += NT) m = fmaxf(m, p[j]);
    float M = block_reduce_max(m, red);
    float s = 0.f;
    for (int j = threadIdx.x; j < NV; j += NT) s += expf(p[j] - M);
    float S_ = block_reduce_sum(s, red);
    if (threadIdx.x == 0)
        rownll[row] = -(p[targets[row]] - M - logf(S_));
}

__global__ void mean_k(const float* __restrict__ rownll, float* __restrict__ out) {
    __shared__ float red[NT];
    float s = 0.f;
    for (int i = threadIdx.x; i < MROWS; i += NT) s += rownll[i];
    float tot = block_reduce_sum(s, red);
    if (threadIdx.x == 0) out[0] = tot / (float)MROWS;
}

// ---------------- launch ----------------
extern "C" void kernel_launch(void* const* d_in, const int* in_sizes, int n_in,
                              void* d_out, int out_size) {
    const int*   tokens   = (const int*)d_in[0];
    const int*   targets  = (const int*)d_in[1];
    const float* word_emb = (const float*)d_in[2];
    const float* pos_emb  = (const float*)d_in[3];
    const float* ln1_w = (const float*)d_in[4];
    const float* ln1_b = (const float*)d_in[5];
    const float* wq = (const float*)d_in[6];
    const float* bq = (const float*)d_in[7];
    const float* wk = (const float*)d_in[8];
    const float* bk = (const float*)d_in[9];
    const float* wv = (const float*)d_in[10];
    const float* bv = (const float*)d_in[11];
    const float* wo = (const float*)d_in[12];
    const float* bo = (const float*)d_in[13];
    const float* ln2_w = (const float*)d_in[14];
    const float* ln2_b = (const float*)d_in[15];
    const float* w1 = (const float*)d_in[16];
    const float* b1 = (const float*)d_in[17];
    const float* w2 = (const float*)d_in[18];
    const float* b2 = (const float*)d_in[19];
    const float* post_w = (const float*)d_in[20];
    const float* post_b = (const float*)d_in[21];
    const float* lnf_w = (const float*)d_in[22];
    const float* lnf_b = (const float*)d_in[23];
    const float* head_w = (const float*)d_in[24];

    float *x, *h, *qf, *kf, *logits, *rownll;
    __nv_bfloat16 *hb, *qb, *kb, *vb, *ob, *mlpb, *wt;
    cudaGetSymbolAddress((void**)&x, g_x);
    cudaGetSymbolAddress((void**)&h, g_h);
    cudaGetSymbolAddress((void**)&qf, g_qf);
    cudaGetSymbolAddress((void**)&kf, g_kf);
    cudaGetSymbolAddress((void**)&logits, g_logits);
    cudaGetSymbolAddress((void**)&rownll, g_rownll);
    cudaGetSymbolAddress((void**)&hb, g_hb);
    cudaGetSymbolAddress((void**)&qb, g_qb);
    cudaGetSymbolAddress((void**)&kb, g_kb);
    cudaGetSymbolAddress((void**)&vb, g_vb);
    cudaGetSymbolAddress((void**)&ob, g_ob);
    cudaGetSymbolAddress((void**)&mlpb, g_mlpb);
    cudaGetSymbolAddress((void**)&wt, g_wt);

    const float scale = 1.0f / 8.0f;
    dim3 tb(32, 8);

    for (int l = 0; l < NL; l++) {
        __nv_bfloat16* base = wt + (size_t)l * WT_L;
        convtrans_k<<<dim3(ND/32, ND/32), tb>>>(wq + (size_t)l*ND*ND, base, ND, ND);
        convtrans_k<<<dim3(ND/32, ND/32), tb>>>(wk + (size_t)l*ND*ND, base + (size_t)ND*ND, ND, ND);
        convtrans_k<<<dim3(ND/32, ND/32), tb>>>(wv + (size_t)l*ND*ND, base + (size_t)2*ND*ND, ND, ND);
        convtrans_k<<<dim3(ND/32, ND/32), tb>>>(wo + (size_t)l*ND*ND, base + (size_t)3*ND*ND, ND, ND);
        convtrans_k<<<dim3(NF/32, ND/32), tb>>>(w1 + (size_t)l*ND*NF, base + (size_t)4*ND*ND, ND, NF);
        convtrans_k<<<dim3(ND/32, NF/32), tb>>>(w2 + (size_t)l*NF*ND, base + (size_t)4*ND*ND + (size_t)NF*ND, NF, ND);
    }
    convtrans_k<<<dim3((NV + 31)/32, ND/32), tb>>>(head_w, wt + WT_HEAD, ND, NV);

    embed_k<<<(MROWS * ND + NT - 1) / NT, NT>>>(tokens, word_emb, pos_emb, x);

    dim3 gdd(ND / GBN, MROWS / GBM);
    for (int l = 0; l < NL; l++) {
        __nv_bfloat16* base = wt + (size_t)l * WT_L;
        __nv_bfloat16* qt  = base;
        __nv_bfloat16* kt  = base + (size_t)ND*ND;
        __nv_bfloat16* vt  = base + (size_t)2*ND*ND;
        __nv_bfloat16* wot = base + (size_t)3*ND*ND;
        __nv_bfloat16* w1t = base + (size_t)4*ND*ND;
        __nv_bfloat16* w2t = base + (size_t)4*ND*ND + (size_t)NF*ND;

        ln_k<<<MROWS, NT>>>(x, ln1_w + l * ND, ln1_b + l * ND, (float*)0, hb);

        gemm_bf<<<gdd, 256>>>(hb, qt, bq + l * ND, (const float*)0, qf, (__nv_bfloat16*)0, MROWS, ND, ND, 0);
        gemm_bf<<<gdd, 256>>>(hb, kt, bk + l * ND, (const float*)0, kf, (__nv_bfloat16*)0, MROWS, ND, ND, 0);
        gemm_bf<<<gdd, 256>>>(hb, vt, bv + l * ND, (const float*)0, (float*)0, vb, MROWS, ND, ND, 0);

        int nrope = NB * NS * NH * 32;
        rope_k<<<(nrope + NT - 1) / NT, NT>>>(qf, qb);
        rope_k<<<(nrope + NT - 1) / NT, NT>>>(kf, kb);

        flash_k<<<dim3(NS / 128, BH), 256>>>(qb, kb, vb, ob, scale);

        gemm_bf<<<gdd, 256>>>(ob, wot, bo + l * ND, x, x, (__nv_bfloat16*)0, MROWS, ND, ND, 0);

        ln_k<<<MROWS, NT>>>(x, ln2_w + l * ND, ln2_b + l * ND, (float*)0, hb);
        gemm_bf<<<dim3(NF / GBN, MROWS / GBM), 256>>>(hb, w1t, b1 + l * NF, (const float*)0,
                                                      (float*)0, mlpb, MROWS, ND, NF, 1);
        gemm_bf<<<gdd, 256>>>(mlpb, w2t, b2 + l * ND, x, x, (__nv_bfloat16*)0, MROWS, NF, ND, 0);
    }

    ln_k<<<MROWS, NT>>>(x, post_w, post_b, h, (__nv_bfloat16*)0);
    ln_k<<<MROWS, NT>>>(h, lnf_w, lnf_b, (float*)0, hb);

    gemm_bf<<<dim3((NV + GBN - 1) / GBN, MROWS / GBM), 256>>>(hb, wt + WT_HEAD, (const float*)0,
                                                              (const float*)0, logits,
                                                              (__nv_bfloat16*)0, MROWS, ND, NV, 0);

    nll_k<<<MROWS, NT>>>(logits, targets, rownll);
    mean_k<<<1, NT>>>(rownll, (float*)d_out);
}

// round 10
// speedup vs baseline: 6.8315x; 1.1323x over previous
#include <cuda_runtime.h>
#include <cuda_bf16.h>
#include <cstdint>
#include <cstddef>
#include <math.h>

typedef unsigned int u32;

#define NL 4
#define NB 2
#define NS 2048
#define ND 1024
#define NH 16
#define DH 64
#define NV 50257
#define NF 4096
#define MROWS (NB*NS)
#define BH (NB*NH)
#define NT 256

#define GBM 128
#define GBN 128
#define GBK 32
#define GP  40
#define STG 4
#define GEMM_SMEM (2 * STG * GBM * GP * 2)   // bytes (A + B, 4 stages)

#define WT_L ((size_t)4*ND*ND + (size_t)NF*ND + (size_t)ND*NF)
#define WT_HEAD ((size_t)4*WT_L)

// ---------------- scratch ----------------
__device__ float g_x[MROWS*ND];
__device__ float g_h[MROWS*ND];
__device__ float g_qf[MROWS*ND];
__device__ float g_kf[MROWS*ND];
__device__ float g_logits[(size_t)MROWS*NV];
__device__ float g_rownll[MROWS];

__device__ __nv_bfloat16 g_hb[MROWS*ND];
__device__ __nv_bfloat16 g_qb[MROWS*ND];
__device__ __nv_bfloat16 g_kb[MROWS*ND];
__device__ __nv_bfloat16 g_vb[MROWS*ND];
__device__ __nv_bfloat16 g_ob[MROWS*ND];
__device__ __nv_bfloat16 g_mlpb[(size_t)MROWS*NF];
__device__ __nv_bfloat16 g_wt[WT_HEAD + (size_t)NV*ND];

// ---------------- helpers ----------------
__device__ __forceinline__ float block_reduce_sum(float v, float* red) {
    int t = threadIdx.x;
    red[t] = v; __syncthreads();
    for (int o = NT/2; o > 0; o >>= 1) {
        if (t < o) red[t] += red[t + o];
        __syncthreads();
    }
    float r = red[0]; __syncthreads();
    return r;
}

__device__ __forceinline__ void ldm_x4(u32* r, u32 addr) {
    asm volatile("ldmatrix.sync.aligned.m8n8.x4.shared.b16 {%0,%1,%2,%3}, [%4];"
                 : "=r"(r[0]), "=r"(r[1]), "=r"(r[2]), "=r"(r[3]) : "r"(addr));
}
__device__ __forceinline__ void mma_bf16(float* c, const u32* a, const u32* b) {
    asm volatile("mma.sync.aligned.m16n8k16.row.col.f32.bf16.bf16.f32 "
                 "{%0,%1,%2,%3}, {%4,%5,%6,%7}, {%8,%9}, {%0,%1,%2,%3};"
                 : "+f"(c[0]), "+f"(c[1]), "+f"(c[2]), "+f"(c[3])
                 : "r"(a[0]), "r"(a[1]), "r"(a[2]), "r"(a[3]), "r"(b[0]), "r"(b[1]));
}
__device__ __forceinline__ u32 pack_bf2(float a, float b) {
    __nv_bfloat162 t = __floats2bfloat162_rn(a, b);
    return *(u32*)&t;
}
__device__ __forceinline__ void cpa16(void* dst, const void* src) {
    u32 d = (u32)__cvta_generic_to_shared(dst);
    asm volatile("cp.async.cg.shared.global [%0], [%1], 16;" :: "r"(d), "l"(src));
}
__device__ __forceinline__ void cpa_commit() {
    asm volatile("cp.async.commit_group;");
}
template<int N_>
__device__ __forceinline__ void cpa_wait() {
    asm volatile("cp.async.wait_group %0;" :: "n"(N_));
}

// ---------------- kernels ----------------
__global__ void embed_k(const int* __restrict__ tokens, const float* __restrict__ we,
                        const float* __restrict__ pe, float* __restrict__ x) {
    int idx = blockIdx.x * blockDim.x + threadIdx.x;
    if (idx >= MROWS * ND) return;
    int d = idx & (ND - 1);
    int row = idx >> 10;
    int s = row & (NS - 1);
    x[idx] = we[(size_t)tokens[row] * ND + d] + pe[(size_t)s * ND + d];
}

// W[K][N] fp32 -> Wt[N][K] bf16
__global__ void convtrans_k(const float* __restrict__ W, __nv_bfloat16* __restrict__ Wt,
                            int K, int N) {
    __shared__ float t[32][33];
    int k0 = blockIdx.y * 32, n0 = blockIdx.x * 32;
    int tx = threadIdx.x, ty = threadIdx.y;
    for (int i = ty; i < 32; i += 8) {
        int n = n0 + tx;
        t[i][tx] = (n < N) ? W[(size_t)(k0 + i) * N + n] : 0.f;
    }
    __syncthreads();
    for (int i = ty; i < 32; i += 8) {
        int n = n0 + i;
        if (n < N) Wt[(size_t)n * K + k0 + tx] = __float2bfloat16(t[tx][i]);
    }
}

__global__ void ln_k(const float* __restrict__ x, const float* __restrict__ w,
                     const float* __restrict__ b, float* __restrict__ outf,
                     __nv_bfloat16* __restrict__ outb) {
    __shared__ float red[NT];
    int row = blockIdx.x;
    const float4* xr = (const float4*)(x + (size_t)row * ND);
    float4 v4 = xr[threadIdx.x];
    float s = v4.x + v4.y + v4.z + v4.w;
    float mean = block_reduce_sum(s, red) * (1.f / ND);
    float dx = v4.x - mean, dy = v4.y - mean, dz = v4.z - mean, dw = v4.w - mean;
    float vs = dx*dx + dy*dy + dz*dz + dw*dw;
    float var = block_reduce_sum(vs, red) * (1.f / ND);
    float rstd = rsqrtf(var + 1e-5f);
    float4 w4 = ((const float4*)w)[threadIdx.x];
    float4 b4 = ((const float4*)b)[threadIdx.x];
    float o0 = dx * rstd * w4.x + b4.x;
    float o1 = dy * rstd * w4.y + b4.y;
    float o2 = dz * rstd * w4.z + b4.z;
    float o3 = dw * rstd * w4.w + b4.w;
    if (outf) {
        float4 o4;
        o4.x = o0; o4.y = o1; o4.z = o2; o4.w = o3;
        ((float4*)(outf + (size_t)row * ND))[threadIdx.x] = o4;
    }
    if (outb) {
        __nv_bfloat16* p = outb + (size_t)row * ND + threadIdx.x * 4;
        p[0] = __float2bfloat16(o0); p[1] = __float2bfloat16(o1);
        p[2] = __float2bfloat16(o2); p[3] = __float2bfloat16(o3);
    }
}

// bf16 tensor-core GEMM, 4-stage cp.async pipeline.
// C[M,N] = A[M,K] @ Bt[N,K]^T (+bias)(+gelu)(+resid)
__global__ __launch_bounds__(256)
void gemm_bf(const __nv_bfloat16* __restrict__ A, const __nv_bfloat16* __restrict__ Bt,
             const float* __restrict__ bias, const float* __restrict__ resid,
             float* __restrict__ Cf, __nv_bfloat16* __restrict__ Cb,
             int M, int K, int N, int act) {
    extern __shared__ __align__(16) __nv_bfloat16 smem[];
    __nv_bfloat16* As = smem;                     // STG * GBM * GP
    __nv_bfloat16* Bs = smem + STG * GBM * GP;

    int tid = threadIdx.x;
    int warp = tid >> 5, lane = tid & 31;
    int wm = (warp & 1) * 64;
    int wn = (warp >> 1) * 32;
    int row0 = blockIdx.y * GBM, col0 = blockIdx.x * GBN;

    // cp.async index map: chunk c -> row c>>2, col (c&3)*8 ; chunks tid, tid+256
    int cr0 = tid >> 2;              // 0..63
    int cc  = (tid & 3) * 8;

    float acc[4][4][4];
    #pragma unroll
    for (int i = 0; i < 4; i++)
        #pragma unroll
        for (int j = 0; j < 4; j++)
            #pragma unroll
            for (int c = 0; c < 4; c++) acc[i][j][c] = 0.f;

    int nk = K / GBK;

    // prologue: stages 0..2
    #pragma unroll
    for (int s = 0; s < STG - 1; s++) {
        if (s < nk) {
            int k0 = s * GBK;
            __nv_bfloat16* as = As + s * GBM * GP;
            __nv_bfloat16* bs = Bs + s * GBM * GP;
            #pragma unroll
            for (int u = 0; u < 2; u++) {
                int r = cr0 + u * 64;
                cpa16(as + r * GP + cc, A + (size_t)(row0 + r) * K + k0 + cc);
                int n = col0 + r;
                if (n < N) cpa16(bs + r * GP + cc, Bt + (size_t)n * K + k0 + cc);
            }
        }
        cpa_commit();
    }

    for (int t = 0; t < nk; t++) {
        cpa_wait<STG - 2>();
        __syncthreads();

        // issue stage t+3
        int tf = t + STG - 1;
        if (tf < nk) {
            int slot = tf & (STG - 1);
            int k0 = tf * GBK;
            __nv_bfloat16* as = As + slot * GBM * GP;
            __nv_bfloat16* bs = Bs + slot * GBM * GP;
            #pragma unroll
            for (int u = 0; u < 2; u++) {
                int r = cr0 + u * 64;
                cpa16(as + r * GP + cc, A + (size_t)(row0 + r) * K + k0 + cc);
                int n = col0 + r;
                if (n < N) cpa16(bs + r * GP + cc, Bt + (size_t)n * K + k0 + cc);
            }
        }
        cpa_commit();

        int slot = t & (STG - 1);
        u32 aB = (u32)__cvta_generic_to_shared(As + slot * GBM * GP);
        u32 bB = (u32)__cvta_generic_to_shared(Bs + slot * GBM * GP);
        #pragma unroll
        for (int ks = 0; ks < 2; ks++) {
            int kk = ks * 16;
            u32 areg[4][4];
            u32 breg[4][2];
            #pragma unroll
            for (int mi = 0; mi < 4; mi++) {
                int r = wm + mi * 16 + (lane & 15);
                int c = kk + (lane >> 4) * 8;
                ldm_x4(areg[mi], aB + (u32)(r * GP + c) * 2u);
            }
            #pragma unroll
            for (int p = 0; p < 2; p++) {
                int r = wn + p * 16 + ((lane >> 4) << 3) + (lane & 7);
                int c = kk + ((lane >> 3) & 1) * 8;
                u32 tmp[4];
                ldm_x4(tmp, bB + (u32)(r * GP + c) * 2u);
                breg[p * 2][0] = tmp[0]; breg[p * 2][1] = tmp[1];
                breg[p * 2 + 1][0] = tmp[2]; breg[p * 2 + 1][1] = tmp[3];
            }
            #pragma unroll
            for (int mi = 0; mi < 4; mi++)
                #pragma unroll
                for (int nj = 0; nj < 4; nj++)
                    mma_bf16(acc[mi][nj], areg[mi], breg[nj]);
        }
        __syncthreads();
    }

    #pragma unroll
    for (int mi = 0; mi < 4; mi++) {
        int rA = row0 + wm + mi * 16 + (lane >> 2);
        #pragma unroll
        for (int nj = 0; nj < 4; nj++) {
            int cA = col0 + wn + nj * 8 + (lane & 3) * 2;
            #pragma unroll
            for (int hh = 0; hh < 2; hh++) {
                int r = rA + hh * 8;
                #pragma unroll
                for (int cc2 = 0; cc2 < 2; cc2++) {
                    int c = cA + cc2;
                    if (c < N) {
                        float v = acc[mi][nj][hh * 2 + cc2];
                        if (bias) v += bias[c];
                        if (act) v = 0.5f * v * (1.f + erff(v * 0.70710678118f));
                        if (resid) v += resid[(size_t)r * N + c];
                        if (Cf) Cf[(size_t)r * N + c] = v;
                        else    Cb[(size_t)r * N + c] = __float2bfloat16(v);
                    }
                }
            }
        }
    }
}

__global__ void rope_k(const float* __restrict__ x, __nv_bfloat16* __restrict__ out) {
    int idx = blockIdx.x * blockDim.x + threadIdx.x;
    if (idx >= NB * NS * NH * 32) return;
    int j = idx & 31;
    int r = idx >> 5;
    int s = (r >> 4) & (NS - 1);
    float inv = powf(10000.f, -(float)(2 * j) / 64.f);
    float fr = (float)s * inv;
    float sn, cs;
    sincosf(fr, &sn, &cs);
    const float* p = x + (size_t)r * DH;
    float x1 = p[j], x2 = p[j + 32];
    out[(size_t)r * DH + j]      = __float2bfloat16(x1 * cs - x2 * sn);
    out[(size_t)r * DH + j + 32] = __float2bfloat16(x2 * cs + x1 * sn);
}

// -------- fused flash attention (causal), 128-row q tiles, 8 warps --------
__global__ __launch_bounds__(256)
void flash_k(const __nv_bfloat16* __restrict__ q, const __nv_bfloat16* __restrict__ kk_,
             const __nv_bfloat16* __restrict__ v, __nv_bfloat16* __restrict__ o,
             float scale) {
    __shared__ __align__(16) __nv_bfloat16 Ks[128 * 72];
    __shared__ __align__(16) __nv_bfloat16 Vs[64 * 136];
    int bh = blockIdx.y;
    int b = bh >> 4, h = bh & 15;
    int i0 = blockIdx.x * 128;
    int tid = threadIdx.x, warp = tid >> 5, lane = tid & 31;
    int wr = warp * 16;
    int colb = (lane & 3) * 2;
    int rq = lane >> 2;

    u32 ksBase = (u32)__cvta_generic_to_shared(Ks);
    u32 vsBase = (u32)__cvta_generic_to_shared(Vs);

    #pragma unroll
    for (int u = 0; u < 4; u++) {
        int idx = tid + u * 256;
        int row = idx >> 3, c = (idx & 7) * 8;
        *(uint4*)&Ks[row * 72 + c] =
            *(const uint4*)(q + (size_t)((b * NS + i0 + row) * NH + h) * DH + c);
    }
    __syncthreads();
    u32 qf[4][4];
    #pragma unroll
    for (int kt = 0; kt < 4; kt++) {
        int r = wr + (lane & 15);
        int c = kt * 16 + (lane >> 4) * 8;
        ldm_x4(qf[kt], ksBase + (u32)(r * 72 + c) * 2u);
    }
    __syncthreads();

    float m_lo = -1e30f, m_hi = -1e30f, l_lo = 0.f, l_hi = 0.f;
    float oa[8][4];
    #pragma unroll
    for (int i = 0; i < 8; i++)
        #pragma unroll
        for (int c = 0; c < 4; c++) oa[i][c] = 0.f;

    for (int j0 = 0; j0 <= i0; j0 += 128) {
        #pragma unroll
        for (int u = 0; u < 4; u++) {
            int idx = tid + u * 256;
            int row = idx >> 3, c = (idx & 7) * 8;
            *(uint4*)&Ks[row * 72 + c] =
                *(const uint4*)(kk_ + (size_t)((b * NS + j0 + row) * NH + h) * DH + c);
        }
        #pragma unroll
        for (int u = 0; u < 4; u++) {
            int dc = (tid >> 7) + u * 2;
            int token = tid & 127;
            uint4 vv = *(const uint4*)(v + (size_t)((b * NS + j0 + token) * NH + h) * DH + dc * 8);
            __nv_bfloat16 tv[8];
            *(uint4*)tv = vv;
            #pragma unroll
            for (int e = 0; e < 8; e++)
                Vs[(dc * 8 + e) * 136 + token] = tv[e];
        }
        __syncthreads();

        float sa[16][4];
        #pragma unroll
        for (int i = 0; i < 16; i++)
            #pragma unroll
            for (int c = 0; c < 4; c++) sa[i][c] = 0.f;
        #pragma unroll
        for (int p = 0; p < 8; p++) {
            #pragma unroll
            for (int kt = 0; kt < 4; kt++) {
                u32 tmp[4];
                int r = p * 16 + ((lane >> 4) << 3) + (lane & 7);
                int c = kt * 16 + ((lane >> 3) & 1) * 8;
                ldm_x4(tmp, ksBase + (u32)(r * 72 + c) * 2u);
                u32 br0[2], br1[2];
                br0[0] = tmp[0]; br0[1] = tmp[1];
                br1[0] = tmp[2]; br1[1] = tmp[3];
                mma_bf16(sa[p * 2], qf[kt], br0);
                mma_bf16(sa[p * 2 + 1], qf[kt], br1);
            }
        }

        bool diag = (j0 == i0);
        float tmax_lo = -1e30f, tmax_hi = -1e30f;
        #pragma unroll
        for (int nt = 0; nt < 16; nt++) {
            #pragma unroll
            for (int cc = 0; cc < 4; cc++) {
                float val = sa[nt][cc] * scale;
                if (diag) {
                    int col = nt * 8 + colb + (cc & 1);
                    int row = wr + rq + ((cc >> 1) << 3);
                    if (col > row) val = -1e30f;
                }
                sa[nt][cc] = val;
                if (cc < 2) tmax_lo = fmaxf(tmax_lo, val);
                else        tmax_hi = fmaxf(tmax_hi, val);
            }
        }
        tmax_lo = fmaxf(tmax_lo, __shfl_xor_sync(0xffffffffu, tmax_lo, 1));
        tmax_lo = fmaxf(tmax_lo, __shfl_xor_sync(0xffffffffu, tmax_lo, 2));
        tmax_hi = fmaxf(tmax_hi, __shfl_xor_sync(0xffffffffu, tmax_hi, 1));
        tmax_hi = fmaxf(tmax_hi, __shfl_xor_sync(0xffffffffu, tmax_hi, 2));

        float mn_lo = fmaxf(m_lo, tmax_lo);
        float mn_hi = fmaxf(m_hi, tmax_hi);
        float al_lo = expf(m_lo - mn_lo);
        float al_hi = expf(m_hi - mn_hi);
        m_lo = mn_lo; m_hi = mn_hi;

        float rs_lo = 0.f, rs_hi = 0.f;
        u32 pa[8][4];
        #pragma unroll
        for (int nt = 0; nt < 16; nt++) {
            float p0 = expf(sa[nt][0] - mn_lo);
            float p1 = expf(sa[nt][1] - mn_lo);
            float p2 = expf(sa[nt][2] - mn_hi);
            float p3 = expf(sa[nt][3] - mn_hi);
            rs_lo += p0 + p1;
            rs_hi += p2 + p3;
            pa[nt >> 1][(nt & 1) * 2 + 0] = pack_bf2(p0, p1);
            pa[nt >> 1][(nt & 1) * 2 + 1] = pack_bf2(p2, p3);
        }
        rs_lo += __shfl_xor_sync(0xffffffffu, rs_lo, 1);
        rs_lo += __shfl_xor_sync(0xffffffffu, rs_lo, 2);
        rs_hi += __shfl_xor_sync(0xffffffffu, rs_hi, 1);
        rs_hi += __shfl_xor_sync(0xffffffffu, rs_hi, 2);
        l_lo = l_lo * al_lo + rs_lo;
        l_hi = l_hi * al_hi + rs_hi;

        #pragma unroll
        for (int nt = 0; nt < 8; nt++) {
            oa[nt][0] *= al_lo; oa[nt][1] *= al_lo;
            oa[nt][2] *= al_hi; oa[nt][3] *= al_hi;
        }

        #pragma unroll
        for (int np = 0; np < 4; np++) {
            #pragma unroll
            for (int kt = 0; kt < 8; kt++) {
                u32 tmp[4];
                int r = np * 16 + ((lane >> 4) << 3) + (lane & 7);
                int c = kt * 16 + ((lane >> 3) & 1) * 8;
                ldm_x4(tmp, vsBase + (u32)(r * 136 + c) * 2u);
                u32 br0[2], br1[2];
                br0[0] = tmp[0]; br0[1] = tmp[1];
                br1[0] = tmp[2]; br1[1] = tmp[3];
                mma_bf16(oa[np * 2], pa[kt], br0);
                mma_bf16(oa[np * 2 + 1], pa[kt], br1);
            }
        }
        __syncthreads();
    }

    float il_lo = 1.f / l_lo, il_hi = 1.f / l_hi;
    int row_lo = i0 + wr + rq;
    #pragma unroll
    for (int nt = 0; nt < 8; nt++) {
        int col = nt * 8 + colb;
        u32 lo2 = pack_bf2(oa[nt][0] * il_lo, oa[nt][1] * il_lo);
        u32 hi2 = pack_bf2(oa[nt][2] * il_hi, oa[nt][3] * il_hi);
        *(u32*)(o + (size_t)((b * NS + row_lo) * NH + h) * DH + col) = lo2;
        *(u32*)(o + (size_t)((b * NS + row_lo + 8) * NH + h) * DH + col) = hi2;
    }
}

// single-pass online logsumexp NLL
__global__ void nll_k(const float* __restrict__ logits, const int* __restrict__ targets,
                      float* __restrict__ rownll) {
    __shared__ float rm[NT], rs[NT];
    int row = blockIdx.x;
    const float* p = logits + (size_t)row * NV;
    float m = -1e30f, s = 0.f;
    for (int j = threadIdx.x; j < NV; j += NT) {
        float v = p[j];
        if (v > m) { s = s * expf(m - v) + 1.f; m = v; }
        else       { s += expf(v - m); }
    }
    int t = threadIdx.x;
    rm[t] = m; rs[t] = s; __syncthreads();
    for (int o = NT/2; o > 0; o >>= 1) {
        if (t < o) {
            float m2 = rm[t + o], s2 = rs[t + o];
            float M = fmaxf(rm[t], m2);
            rs[t] = rs[t] * expf(rm[t] - M) + s2 * expf(m2 - M);
            rm[t] = M;
        }
        __syncthreads();
    }
    if (t == 0)
        rownll[row] = -(p[targets[row]] - rm[0] - logf(rs[0]));
}

__global__ void mean_k(const float* __restrict__ rownll, float* __restrict__ out) {
    __shared__ float red[NT];
    float s = 0.f;
    for (int i = threadIdx.x; i < MROWS; i += NT) s += rownll[i];
    float tot = block_reduce_sum(s, red);
    if (threadIdx.x == 0) out[0] = tot / (float)MROWS;
}

// ---------------- launch ----------------
extern "C" void kernel_launch(void* const* d_in, const int* in_sizes, int n_in,
                              void* d_out, int out_size) {
    const int*   tokens   = (const int*)d_in[0];
    const int*   targets  = (const int*)d_in[1];
    const float* word_emb = (const float*)d_in[2];
    const float* pos_emb  = (const float*)d_in[3];
    const float* ln1_w = (const float*)d_in[4];
    const float* ln1_b = (const float*)d_in[5];
    const float* wq = (const float*)d_in[6];
    const float* bq = (const float*)d_in[7];
    const float* wk = (const float*)d_in[8];
    const float* bk = (const float*)d_in[9];
    const float* wv = (const float*)d_in[10];
    const float* bv = (const float*)d_in[11];
    const float* wo = (const float*)d_in[12];
    const float* bo = (const float*)d_in[13];
    const float* ln2_w = (const float*)d_in[14];
    const float* ln2_b = (const float*)d_in[15];
    const float* w1 = (const float*)d_in[16];
    const float* b1 = (const float*)d_in[17];
    const float* w2 = (const float*)d_in[18];
    const float* b2 = (const float*)d_in[19];
    const float* post_w = (const float*)d_in[20];
    const float* post_b = (const float*)d_in[21];
    const float* lnf_w = (const float*)d_in[22];
    const float* lnf_b = (const float*)d_in[23];
    const float* head_w = (const float*)d_in[24];

    float *x, *h, *qf, *kf, *logits, *rownll;
    __nv_bfloat16 *hb, *qb, *kb, *vb, *ob, *mlpb, *wt;
    cudaGetSymbolAddress((void**)&x, g_x);
    cudaGetSymbolAddress((void**)&h, g_h);
    cudaGetSymbolAddress((void**)&qf, g_qf);
    cudaGetSymbolAddress((void**)&kf, g_kf);
    cudaGetSymbolAddress((void**)&logits, g_logits);
    cudaGetSymbolAddress((void**)&rownll, g_rownll);
    cudaGetSymbolAddress((void**)&hb, g_hb);
    cudaGetSymbolAddress((void**)&qb, g_qb);
    cudaGetSymbolAddress((void**)&kb, g_kb);
    cudaGetSymbolAddress((void**)&vb, g_vb);
    cudaGetSymbolAddress((void**)&ob, g_ob);
    cudaGetSymbolAddress((void**)&mlpb, g_mlpb);
    cudaGetSymbolAddress((void**)&wt, g_wt);

    static int smem_set = 0;
    if (!smem_set) {
        cudaFuncSetAttribute(gemm_bf, cudaFuncAttributeMaxDynamicSharedMemorySize, GEMM_SMEM);
        smem_set = 1;
    }

    const float scale = 1.0f / 8.0f;
    dim3 tb(32, 8);

    for (int l = 0; l < NL; l++) {
        __nv_bfloat16* base = wt + (size_t)l * WT_L;
        convtrans_k<<<dim3(ND/32, ND/32), tb>>>(wq + (size_t)l*ND*ND, base, ND, ND);
        convtrans_k<<<dim3(ND/32, ND/32), tb>>>(wk + (size_t)l*ND*ND, base + (size_t)ND*ND, ND, ND);
        convtrans_k<<<dim3(ND/32, ND/32), tb>>>(wv + (size_t)l*ND*ND, base + (size_t)2*ND*ND, ND, ND);
        convtrans_k<<<dim3(ND/32, ND/32), tb>>>(wo + (size_t)l*ND*ND, base + (size_t)3*ND*ND, ND, ND);
        convtrans_k<<<dim3(NF/32, ND/32), tb>>>(w1 + (size_t)l*ND*NF, base + (size_t)4*ND*ND, ND, NF);
        convtrans_k<<<dim3(ND/32, NF/32), tb>>>(w2 + (size_t)l*NF*ND, base + (size_t)4*ND*ND + (size_t)NF*ND, NF, ND);
    }
    convtrans_k<<<dim3((NV + 31)/32, ND/32), tb>>>(head_w, wt + WT_HEAD, ND, NV);

    embed_k<<<(MROWS * ND + NT - 1) / NT, NT>>>(tokens, word_emb, pos_emb, x);

    dim3 gdd(ND / GBN, MROWS / GBM);
    for (int l = 0; l < NL; l++) {
        __nv_bfloat16* base = wt + (size_t)l * WT_L;
        __nv_bfloat16* qt  = base;
        __nv_bfloat16* kt  = base + (size_t)ND*ND;
        __nv_bfloat16* vt  = base + (size_t)2*ND*ND;
        __nv_bfloat16* wot = base + (size_t)3*ND*ND;
        __nv_bfloat16* w1t = base + (size_t)4*ND*ND;
        __nv_bfloat16* w2t = base + (size_t)4*ND*ND + (size_t)NF*ND;

        ln_k<<<MROWS, NT>>>(x, ln1_w + l * ND, ln1_b + l * ND, (float*)0, hb);

        gemm_bf<<<gdd, 256, GEMM_SMEM>>>(hb, qt, bq + l * ND, (const float*)0, qf, (__nv_bfloat16*)0, MROWS, ND, ND, 0);
        gemm_bf<<<gdd, 256, GEMM_SMEM>>>(hb, kt, bk + l * ND, (const float*)0, kf, (__nv_bfloat16*)0, MROWS, ND, ND, 0);
        gemm_bf<<<gdd, 256, GEMM_SMEM>>>(hb, vt, bv + l * ND, (const float*)0, (float*)0, vb, MROWS, ND, ND, 0);

        int nrope = NB * NS * NH * 32;
        rope_k<<<(nrope + NT - 1) / NT, NT>>>(qf, qb);
        rope_k<<<(nrope + NT - 1) / NT, NT>>>(kf, kb);

        flash_k<<<dim3(NS / 128, BH), 256>>>(qb, kb, vb, ob, scale);

        gemm_bf<<<gdd, 256, GEMM_SMEM>>>(ob, wot, bo + l * ND, x, x, (__nv_bfloat16*)0, MROWS, ND, ND, 0);

        ln_k<<<MROWS, NT>>>(x, ln2_w + l * ND, ln2_b + l * ND, (float*)0, hb);
        gemm_bf<<<dim3(NF / GBN, MROWS / GBM), 256, GEMM_SMEM>>>(hb, w1t, b1 + l * NF, (const float*)0,
                                                                 (float*)0, mlpb, MROWS, ND, NF, 1);
        gemm_bf<<<gdd, 256, GEMM_SMEM>>>(mlpb, w2t, b2 + l * ND, x, x, (__nv_bfloat16*)0, MROWS, NF, ND, 0);
    }

    ln_k<<<MROWS, NT>>>(x, post_w, post_b, h, (__nv_bfloat16*)0);
    ln_k<<<MROWS, NT>>>(h, lnf_w, lnf_b, (float*)0, hb);

    gemm_bf<<<dim3((NV + GBN - 1) / GBN, MROWS / GBM), 256, GEMM_SMEM>>>(hb, wt + WT_HEAD, (const float*)0,
                                                                         (const float*)0, logits,
                                                                         (__nv_bfloat16*)0, MROWS, ND, NV, 0);

    nll_k<<<MROWS, NT>>>(logits, targets, rownll);
    mean_k<<<1, NT>>>(rownll, (float*)d_out);
}